// round 1
// baseline (speedup 1.0000x reference)
#include <cuda_runtime.h>
#include <cuda_bf16.h>
#include <cstdint>
#include <cstdio>

// Problem constants
#define BSZ   16
#define SEQ   12
#define NN    512
#define DIM   256
#define NH    8
#define NL    2
#define TOPK  16
#define DFF   1024
#define DH    32
#define NB    (BSZ*NN)        // 8192 sequences
#define ME    (NB*TOPK)       // 131072 encoder tokens

// ---------------- device scratch (static; no runtime allocation) ------------
__device__ float g_src [ (size_t)ME*DIM ];
__device__ float g_y   [ (size_t)ME*DIM ];
__device__ float g_q   [ (size_t)ME*DIM ];
__device__ float g_k   [ (size_t)ME*DIM ];
__device__ float g_v   [ (size_t)ME*DIM ];
__device__ float g_mem [ (size_t)ME*DIM ];
__device__ float g_ffn [ (size_t)ME*DFF ];
__device__ float g_tgt [ (size_t)NB*DIM ];
__device__ float g_ty  [ (size_t)NB*DIM ];
__device__ float g_t1  [ (size_t)NB*DIM ];
__device__ float g_t2  [ (size_t)NB*DIM ];
__device__ float g_tffn[ (size_t)NB*DFF ];
__device__ int   g_topk[ NN*TOPK ];

// ---------------- top-K (exact, stable tie-break = smaller index) -----------
__global__ void __launch_bounds__(256) topk_kernel(const float* __restrict__ A,
                                                   int* __restrict__ topk) {
    __shared__ float vals[512];
    __shared__ float rv[256];
    __shared__ int   ri[256];
    int r = blockIdx.x, t = threadIdx.x;
    vals[t]       = A[(size_t)r*512 + t];
    vals[t + 256] = A[(size_t)r*512 + t + 256];
    __syncthreads();
    for (int it = 0; it < TOPK; ++it) {
        float bv = vals[t]; int bi = t;
        float v2 = vals[t + 256];
        if (v2 > bv) { bv = v2; bi = t + 256; }       // tie -> keep smaller idx
        rv[t] = bv; ri[t] = bi;
        __syncthreads();
        for (int s = 128; s > 0; s >>= 1) {
            if (t < s) {
                float ov = rv[t + s]; int oi = ri[t + s];
                if (ov > rv[t] || (ov == rv[t] && oi < ri[t])) { rv[t] = ov; ri[t] = oi; }
            }
            __syncthreads();
        }
        if (t == 0) { topk[r*TOPK + it] = ri[0]; vals[ri[0]] = -3.402823466e38f; }
        __syncthreads();
    }
}

// ---------------- embeddings + positional encoding --------------------------
__device__ __forceinline__ float pe_val(int pos, int d) {
    int e = d & ~1;
    float div = __expf(-(float)e * (logf(10000.0f) / (float)DIM));
    float ang = (float)pos * div;
    return (d & 1) ? cosf(ang) : sinf(ang);
}

__global__ void __launch_bounds__(256) embed_src_kernel(
        const float* __restrict__ x_c, const float* __restrict__ Wsrc,
        const int* __restrict__ topk, float* __restrict__ src) {
    __shared__ float xs[SEQ];
    int tok = blockIdx.x;               // 0..ME-1
    int t   = threadIdx.x;              // d
    int bn  = tok / TOPK, kk = tok % TOPK;
    int b   = bn / NN,    n  = bn % NN;
    int node = topk[n*TOPK + kk];
    if (t < SEQ) xs[t] = x_c[((size_t)b*SEQ + t)*NN + node];
    __syncthreads();
    float acc = 0.f;
    #pragma unroll
    for (int s = 0; s < SEQ; ++s) acc += xs[s] * Wsrc[s*DIM + t];
    src[(size_t)tok*DIM + t] = acc * 16.0f + pe_val(kk, t);
}

__global__ void __launch_bounds__(256) embed_tgt_kernel(
        const float* __restrict__ x_c, const float* __restrict__ Wtgt,
        float* __restrict__ tgt) {
    __shared__ float xs[SEQ];
    int bn = blockIdx.x, t = threadIdx.x;
    int b = bn / NN, n = bn % NN;
    if (t < SEQ) xs[t] = x_c[((size_t)b*SEQ + t)*NN + n];
    __syncthreads();
    float acc = 0.f;
    #pragma unroll
    for (int s = 0; s < SEQ; ++s) acc += xs[s] * Wtgt[s*DIM + t];
    float pe0 = (t & 1) ? 1.0f : 0.0f;  // pos 0: sin(0)=0, cos(0)=1
    tgt[(size_t)bn*DIM + t] = acc * 16.0f + pe0;
}

// ---------------- layernorm (warp per row, 256 cols) ------------------------
__global__ void __launch_bounds__(256) ln_kernel(const float* __restrict__ in,
                                                 float* __restrict__ out) {
    int wid = threadIdx.x >> 5, lane = threadIdx.x & 31;
    size_t row = (size_t)blockIdx.x * 8 + wid;
    const float* p = in + row*DIM;
    float x[8];
    #pragma unroll
    for (int i = 0; i < 8; ++i) x[i] = p[lane + 32*i];
    float s = 0.f;
    #pragma unroll
    for (int i = 0; i < 8; ++i) s += x[i];
    #pragma unroll
    for (int o = 16; o > 0; o >>= 1) s += __shfl_xor_sync(0xffffffffu, s, o);
    float m = s * (1.0f/DIM);
    float v = 0.f;
    #pragma unroll
    for (int i = 0; i < 8; ++i) { float d = x[i] - m; v += d*d; }
    #pragma unroll
    for (int o = 16; o > 0; o >>= 1) v += __shfl_xor_sync(0xffffffffu, v, o);
    float rs = rsqrtf(v * (1.0f/DIM) + 1e-6f);
    float* q = out + row*DIM;
    #pragma unroll
    for (int i = 0; i < 8; ++i) q[lane + 32*i] = (x[i] - m) * rs;
}

// ---------------- fp32 GEMM, C[M,N] (op)= A[M,Kd] @ W[Kd,N] -----------------
// MODE 0: C = AB   MODE 1: C += AB   MODE 2: C = relu(AB)
template<int MODE>
__global__ void __launch_bounds__(256) gemm_kernel(
        const float* __restrict__ A, const float* __restrict__ W,
        float* __restrict__ C, int M, int Kd, int N) {
    const int BM = 128, BN = 64, BK = 16;
    __shared__ float As[BK][BM + 4];   // pad to avoid STS conflicts
    __shared__ float Ws[BK][BN];
    int t  = threadIdx.x;
    int m0 = blockIdx.y * BM, n0 = blockIdx.x * BN;
    int tx = t & 15, ty = t >> 4;
    float acc[8][4];
    #pragma unroll
    for (int i = 0; i < 8; ++i)
        #pragma unroll
        for (int j = 0; j < 4; ++j) acc[i][j] = 0.f;

    for (int k0 = 0; k0 < Kd; k0 += BK) {
        #pragma unroll
        for (int i = 0; i < 8; ++i) {
            int e = t + i*256; int m = e >> 4, kk = e & 15;
            As[kk][m] = A[(size_t)(m0 + m)*Kd + k0 + kk];
        }
        #pragma unroll
        for (int i = 0; i < 4; ++i) {
            int e = t + i*256; int kk = e >> 6, n = e & 63;
            Ws[kk][n] = W[(size_t)(k0 + kk)*N + n0 + n];
        }
        __syncthreads();
        #pragma unroll
        for (int kk = 0; kk < BK; ++kk) {
            float4 b4 = *reinterpret_cast<const float4*>(&Ws[kk][tx*4]);
            float4 a0 = *reinterpret_cast<const float4*>(&As[kk][ty*8]);
            float4 a1 = *reinterpret_cast<const float4*>(&As[kk][ty*8 + 4]);
            float a[8] = {a0.x,a0.y,a0.z,a0.w,a1.x,a1.y,a1.z,a1.w};
            float b[4] = {b4.x,b4.y,b4.z,b4.w};
            #pragma unroll
            for (int i = 0; i < 8; ++i)
                #pragma unroll
                for (int j = 0; j < 4; ++j) acc[i][j] += a[i]*b[j];
        }
        __syncthreads();
    }
    #pragma unroll
    for (int i = 0; i < 8; ++i) {
        size_t idx = (size_t)(m0 + ty*8 + i)*N + n0 + tx*4;
        float4 r;
        if (MODE == 1) {
            float4 c = *reinterpret_cast<const float4*>(&C[idx]);
            r.x = c.x + acc[i][0]; r.y = c.y + acc[i][1];
            r.z = c.z + acc[i][2]; r.w = c.w + acc[i][3];
        } else if (MODE == 2) {
            r.x = fmaxf(acc[i][0], 0.f); r.y = fmaxf(acc[i][1], 0.f);
            r.z = fmaxf(acc[i][2], 0.f); r.w = fmaxf(acc[i][3], 0.f);
        } else {
            r.x = acc[i][0]; r.y = acc[i][1]; r.z = acc[i][2]; r.w = acc[i][3];
        }
        *reinterpret_cast<float4*>(&C[idx]) = r;
    }
}

// ---------------- encoder self-attention (one CTA per sequence) -------------
__global__ void __launch_bounds__(256) enc_attn_kernel(
        const float* __restrict__ Q, const float* __restrict__ Kv,
        const float* __restrict__ V, float* __restrict__ O) {
    __shared__ float qs[TOPK*DIM];
    __shared__ float ks[TOPK*DIM];
    __shared__ float vs[TOPK*DIM];
    int bn = blockIdx.x, t = threadIdx.x;
    size_t base = (size_t)bn * TOPK * DIM;
    for (int i = t; i < TOPK*DIM; i += 256) {
        qs[i] = Q[base + i]; ks[i] = Kv[base + i]; vs[i] = V[base + i];
    }
    __syncthreads();
    const float scale = 0.17677669529663687f; // 1/sqrt(32)
    float sc[8];
    #pragma unroll
    for (int i = 0; i < 8; ++i) {
        int e = t + i*256;                 // e = h*256 + qi*16 + kj
        int h = e >> 8, qi = (e >> 4) & 15, kj = e & 15;
        const float* qp = &qs[qi*DIM + h*DH];
        const float* kp = &ks[kj*DIM + h*DH];
        float d = 0.f;
        #pragma unroll
        for (int x = 0; x < DH; ++x) d += qp[x]*kp[x];
        sc[i] = d * scale;
    }
    __syncthreads();
    float* S = qs;                         // q no longer needed; reuse for scores
    #pragma unroll
    for (int i = 0; i < 8; ++i) S[t + i*256] = sc[i];
    __syncthreads();
    if (t < 128) {                         // one row (h,qi) per thread
        float* row = &S[t*16];
        float mx = row[0];
        #pragma unroll
        for (int j = 1; j < 16; ++j) mx = fmaxf(mx, row[j]);
        float sum = 0.f;
        #pragma unroll
        for (int j = 0; j < 16; ++j) { float a = expf(row[j]-mx); row[j] = a; sum += a; }
        float inv = 1.0f / sum;
        #pragma unroll
        for (int j = 0; j < 16; ++j) row[j] *= inv;
    }
    __syncthreads();
    for (int i = t; i < TOPK*DIM; i += 256) {
        int qi = i >> 8, c = i & 255, h = c >> 5;
        const float* row = &S[(h*16 + qi)*16];
        float acc = 0.f;
        #pragma unroll
        for (int kj = 0; kj < 16; ++kj) acc += row[kj] * vs[kj*DIM + c];
        O[base + i] = acc;
    }
}

// ---------------- decoder cross-attention (query len 1) ---------------------
__global__ void __launch_bounds__(256) cross_attn_kernel(
        const float* __restrict__ Q, const float* __restrict__ Kv,
        const float* __restrict__ V, float* __restrict__ O) {
    __shared__ float ks[TOPK*DIM];
    __shared__ float vs[TOPK*DIM];
    __shared__ float qv[DIM];
    __shared__ float S[NH*TOPK];
    int bn = blockIdx.x, t = threadIdx.x;
    size_t kb = (size_t)bn * TOPK * DIM;
    qv[t] = Q[(size_t)bn*DIM + t];
    for (int i = t; i < TOPK*DIM; i += 256) { ks[i] = Kv[kb + i]; vs[i] = V[kb + i]; }
    __syncthreads();
    const float scale = 0.17677669529663687f;
    if (t < NH*TOPK) {
        int h = t >> 4, kj = t & 15;
        float d = 0.f;
        #pragma unroll
        for (int x = 0; x < DH; ++x) d += qv[h*DH + x] * ks[kj*DIM + h*DH + x];
        S[t] = d * scale;
    }
    __syncthreads();
    if (t < NH) {
        float* row = &S[t*16];
        float mx = row[0];
        #pragma unroll
        for (int j = 1; j < 16; ++j) mx = fmaxf(mx, row[j]);
        float sum = 0.f;
        #pragma unroll
        for (int j = 0; j < 16; ++j) { float a = expf(row[j]-mx); row[j] = a; sum += a; }
        float inv = 1.0f / sum;
        #pragma unroll
        for (int j = 0; j < 16; ++j) row[j] *= inv;
    }
    __syncthreads();
    {
        int c = t, h = c >> 5;
        float acc = 0.f;
        #pragma unroll
        for (int kj = 0; kj < 16; ++kj) acc += S[h*16 + kj] * vs[kj*DIM + c];
        O[(size_t)bn*DIM + c] = acc;
    }
}

// ---------------- final LN + generator --------------------------------------
__global__ void __launch_bounds__(256) gen_kernel(
        const float* __restrict__ tgt, const float* __restrict__ Wgen,
        float* __restrict__ out) {
    __shared__ float red[256];
    __shared__ float y[256];
    __shared__ float stat[2];
    int bn = blockIdx.x, t = threadIdx.x;
    float v = tgt[(size_t)bn*DIM + t];
    red[t] = v; __syncthreads();
    for (int s = 128; s > 0; s >>= 1) { if (t < s) red[t] += red[t + s]; __syncthreads(); }
    if (t == 0) stat[0] = red[0] * (1.0f/DIM);
    __syncthreads();
    float d = v - stat[0];
    red[t] = d*d; __syncthreads();
    for (int s = 128; s > 0; s >>= 1) { if (t < s) red[t] += red[t + s]; __syncthreads(); }
    if (t == 0) stat[1] = rsqrtf(red[0] * (1.0f/DIM) + 1e-6f);
    __syncthreads();
    y[t] = d * stat[1];
    __syncthreads();
    if (t < SEQ) {
        float acc = 0.f;
        for (int dd = 0; dd < DIM; ++dd) acc += y[dd] * Wgen[dd*SEQ + t];
        out[(size_t)bn*SEQ + t] = acc;
    }
}

// ---------------- host orchestration -----------------------------------------
static inline dim3 ggrid(int M, int N) { return dim3(N/64, M/128); }

extern "C" void kernel_launch(void* const* d_in, const int* in_sizes, int n_in,
                              void* d_out, int out_size) {
    (void)in_sizes; (void)n_in; (void)out_size;
    const float* x_c      = (const float*)d_in[0];
    const float* A        = (const float*)d_in[1];
    const float* Wsrc     = (const float*)d_in[2];
    const float* Wtgt     = (const float*)d_in[3];
    const float* enc_attn = (const float*)d_in[4];
    const float* enc_ffn1 = (const float*)d_in[5];
    const float* enc_ffn2 = (const float*)d_in[6];
    const float* dec_self = (const float*)d_in[7];
    const float* dec_cross= (const float*)d_in[8];
    const float* dec_ffn1 = (const float*)d_in[9];
    const float* dec_ffn2 = (const float*)d_in[10];
    const float* Wgen     = (const float*)d_in[11];
    float* out = (float*)d_out;

    float *src,*y,*q,*k,*v,*mem,*ffn,*tgt,*ty,*t1,*t2,*tffn; int* topk;
    cudaGetSymbolAddress((void**)&src,  g_src);
    cudaGetSymbolAddress((void**)&y,    g_y);
    cudaGetSymbolAddress((void**)&q,    g_q);
    cudaGetSymbolAddress((void**)&k,    g_k);
    cudaGetSymbolAddress((void**)&v,    g_v);
    cudaGetSymbolAddress((void**)&mem,  g_mem);
    cudaGetSymbolAddress((void**)&ffn,  g_ffn);
    cudaGetSymbolAddress((void**)&tgt,  g_tgt);
    cudaGetSymbolAddress((void**)&ty,   g_ty);
    cudaGetSymbolAddress((void**)&t1,   g_t1);
    cudaGetSymbolAddress((void**)&t2,   g_t2);
    cudaGetSymbolAddress((void**)&tffn, g_tffn);
    cudaGetSymbolAddress((void**)&topk, g_topk);

    const size_t WSZ = (size_t)DIM*DIM;   // 65536

    topk_kernel<<<NN, 256>>>(A, topk);
    embed_src_kernel<<<ME, 256>>>(x_c, Wsrc, topk, src);
    embed_tgt_kernel<<<NB, 256>>>(x_c, Wtgt, tgt);

    // ---- encoder ----
    for (int l = 0; l < NL; ++l) {
        const float* Wq = enc_attn + ((size_t)l*4 + 0)*WSZ;
        const float* Wk = enc_attn + ((size_t)l*4 + 1)*WSZ;
        const float* Wv = enc_attn + ((size_t)l*4 + 2)*WSZ;
        const float* Wo = enc_attn + ((size_t)l*4 + 3)*WSZ;
        ln_kernel<<<ME/8, 256>>>(src, y);
        gemm_kernel<0><<<ggrid(ME,DIM), 256>>>(y, Wq, q, ME, DIM, DIM);
        gemm_kernel<0><<<ggrid(ME,DIM), 256>>>(y, Wk, k, ME, DIM, DIM);
        gemm_kernel<0><<<ggrid(ME,DIM), 256>>>(y, Wv, v, ME, DIM, DIM);
        enc_attn_kernel<<<NB, 256>>>(q, k, v, y);          // y := attn output
        gemm_kernel<1><<<ggrid(ME,DIM), 256>>>(y, Wo, src, ME, DIM, DIM);
        ln_kernel<<<ME/8, 256>>>(src, y);
        gemm_kernel<2><<<ggrid(ME,DFF), 256>>>(y, enc_ffn1 + (size_t)l*DIM*DFF, ffn, ME, DIM, DFF);
        gemm_kernel<1><<<ggrid(ME,DIM), 256>>>(ffn, enc_ffn2 + (size_t)l*DFF*DIM, src, ME, DFF, DIM);
    }
    ln_kernel<<<ME/8, 256>>>(src, mem);

    // ---- decoder ----
    for (int l = 0; l < NL; ++l) {
        const float* Wsv = dec_self + ((size_t)l*4 + 2)*WSZ;
        const float* Wso = dec_self + ((size_t)l*4 + 3)*WSZ;
        // self-attn with seq len 1: softmax==1 -> o = v
        ln_kernel<<<NB/8, 256>>>(tgt, ty);
        gemm_kernel<0><<<ggrid(NB,DIM), 256>>>(ty, Wsv, t1, NB, DIM, DIM);
        gemm_kernel<1><<<ggrid(NB,DIM), 256>>>(t1, Wso, tgt, NB, DIM, DIM);
        // cross-attn
        const float* Wcq = dec_cross + ((size_t)l*4 + 0)*WSZ;
        const float* Wck = dec_cross + ((size_t)l*4 + 1)*WSZ;
        const float* Wcv = dec_cross + ((size_t)l*4 + 2)*WSZ;
        const float* Wco = dec_cross + ((size_t)l*4 + 3)*WSZ;
        ln_kernel<<<NB/8, 256>>>(tgt, ty);
        gemm_kernel<0><<<ggrid(NB,DIM), 256>>>(ty, Wcq, t1, NB, DIM, DIM);
        gemm_kernel<0><<<ggrid(ME,DIM), 256>>>(mem, Wck, k, ME, DIM, DIM);
        gemm_kernel<0><<<ggrid(ME,DIM), 256>>>(mem, Wcv, v, ME, DIM, DIM);
        cross_attn_kernel<<<NB, 256>>>(t1, k, v, t2);
        gemm_kernel<1><<<ggrid(NB,DIM), 256>>>(t2, Wco, tgt, NB, DIM, DIM);
        // FFN
        ln_kernel<<<NB/8, 256>>>(tgt, ty);
        gemm_kernel<2><<<ggrid(NB,DFF), 256>>>(ty, dec_ffn1 + (size_t)l*DIM*DFF, tffn, NB, DIM, DFF);
        gemm_kernel<1><<<ggrid(NB,DIM), 256>>>(tffn, dec_ffn2 + (size_t)l*DFF*DIM, tgt, NB, DFF, DIM);
    }

    gen_kernel<<<NB, 256>>>(tgt, Wgen, out);
}

// round 5
// speedup vs baseline: 1.7272x; 1.7272x over previous
#include <cuda_runtime.h>
#include <cuda_bf16.h>
#include <cstdint>

// Problem constants
#define BSZ   16
#define SEQ   12
#define NN    512
#define DIM   256
#define NH    8
#define NL    2
#define TOPK  16
#define DFF   1024
#define DH    32
#define NB    (BSZ*NN)        // 8192 sequences
#define ME    (NB*TOPK)       // 131072 encoder tokens

// ===================== helpers ==============================================
__device__ __forceinline__ uint32_t smem_to_u32(const void* p) {
    uint32_t a;
    asm("{ .reg .u64 t; cvta.to.shared.u64 t, %1; cvt.u32.u64 %0, t; }"
        : "=r"(a) : "l"(p));
    return a;
}
__device__ __forceinline__ void cpa16(uint32_t saddr, const void* g) {
    asm volatile("cp.async.cg.shared.global [%0], [%1], 16;\n" :: "r"(saddr), "l"(g));
}
#define CPA_COMMIT()  asm volatile("cp.async.commit_group;\n" ::: "memory")
#define CPA_WAIT1()   asm volatile("cp.async.wait_group 1;\n" ::: "memory")
#define CPA_WAIT0()   asm volatile("cp.async.wait_group 0;\n" ::: "memory")

__device__ __forceinline__ void ldm4(uint32_t* r, uint32_t a) {
    asm volatile("ldmatrix.sync.aligned.m8n8.x4.shared.b16 {%0,%1,%2,%3}, [%4];"
        : "=r"(r[0]), "=r"(r[1]), "=r"(r[2]), "=r"(r[3]) : "r"(a));
}
__device__ __forceinline__ void mma16816(float* c, const uint32_t* a, const uint32_t* b) {
    asm volatile("mma.sync.aligned.m16n8k16.row.col.f32.bf16.bf16.f32 "
        "{%0,%1,%2,%3}, {%4,%5,%6,%7}, {%8,%9}, {%0,%1,%2,%3};"
        : "+f"(c[0]), "+f"(c[1]), "+f"(c[2]), "+f"(c[3])
        : "r"(a[0]), "r"(a[1]), "r"(a[2]), "r"(a[3]), "r"(b[0]), "r"(b[1]));
}

// bf16 split helpers
__device__ __forceinline__ void split_bf(float x, __nv_bfloat16& h, __nv_bfloat16& l) {
    h = __float2bfloat16(x);
    l = __float2bfloat16(x - __bfloat162float(h));
}
__device__ __forceinline__ uint32_t pack2(__nv_bfloat16 a, __nv_bfloat16 b) {
    __nv_bfloat162 p(a, b);
    return *reinterpret_cast<uint32_t*>(&p);
}

// ===================== device scratch ========================================
__device__ float g_src [ (size_t)ME*DIM ];
__device__ float g_q   [ (size_t)ME*DIM ];
__device__ float g_k   [ (size_t)ME*DIM ];
__device__ float g_v   [ (size_t)ME*DIM ];
__device__ float g_tgt [ (size_t)NB*DIM ];
__device__ float g_t1  [ (size_t)NB*DIM ];
__device__ int   g_topk[ NN*TOPK ];

__device__ __nv_bfloat16 g_yh  [ (size_t)ME*DIM ];
__device__ __nv_bfloat16 g_yl  [ (size_t)ME*DIM ];
__device__ __nv_bfloat16 g_memh[ (size_t)ME*DIM ];
__device__ __nv_bfloat16 g_meml[ (size_t)ME*DIM ];
__device__ __nv_bfloat16 g_ffnh[ (size_t)ME*DFF ];
__device__ __nv_bfloat16 g_ffnl[ (size_t)ME*DFF ];
__device__ __nv_bfloat16 g_tyh [ (size_t)NB*DIM ];
__device__ __nv_bfloat16 g_tyl [ (size_t)NB*DIM ];
__device__ __nv_bfloat16 g_t1h [ (size_t)NB*DIM ];
__device__ __nv_bfloat16 g_t1l [ (size_t)NB*DIM ];
__device__ __nv_bfloat16 g_t2h [ (size_t)NB*DIM ];
__device__ __nv_bfloat16 g_t2l [ (size_t)NB*DIM ];
__device__ __nv_bfloat16 g_tfh [ (size_t)NB*DFF ];
__device__ __nv_bfloat16 g_tfl [ (size_t)NB*DFF ];

// transposed+split weights
#define W_ENC_ATTN  0
#define W_DEC_SELF  524288
#define W_DEC_CROSS 1048576
#define W_ENC_FFN1  1572864
#define W_ENC_FFN2  2097152
#define W_DEC_FFN1  2621440
#define W_DEC_FFN2  3145728
#define W_TOTAL     3670016
__device__ __nv_bfloat16 g_wh[ W_TOTAL ];
__device__ __nv_bfloat16 g_wl[ W_TOTAL ];

// ===================== weight transpose + split ==============================
// in: W[K,N] fp32 row-major; out: Wt_hi/lo [N,K] bf16 row-major
__global__ void __launch_bounds__(256) wsplit_kernel(
        const float* __restrict__ W, __nv_bfloat16* __restrict__ Wh,
        __nv_bfloat16* __restrict__ Wl, int K, int N) {
    __shared__ float ts[32][33];
    int k0 = blockIdx.y * 32, n0 = blockIdx.x * 32;
    int tx = threadIdx.x & 31, ty = threadIdx.x >> 5;   // 32x8
    #pragma unroll
    for (int i = 0; i < 32; i += 8)
        ts[ty + i][tx] = W[(size_t)(k0 + ty + i) * N + n0 + tx];
    __syncthreads();
    #pragma unroll
    for (int i = 0; i < 32; i += 8) {
        float x = ts[tx][ty + i];
        __nv_bfloat16 h, l; split_bf(x, h, l);
        size_t o = (size_t)(n0 + ty + i) * K + k0 + tx;
        Wh[o] = h; Wl[o] = l;
    }
}

// ===================== mma.sync split-bf16 GEMM ==============================
// C[M,N] (op)= A[M,K] * W[K,N].  A = (Ah,Al) bf16 [M,K]; W = (Bh,Bl) bf16 [N,K].
// MODE 0: C=AB (fp32)  1: C+=AB (fp32)  2: Ch/Cl=split(relu(AB))  3: Ch/Cl=split(AB)
// CTA tile 128x128, BK=32, 8 warps (warp tile 64x32). 2-stage cp.async pipeline.
// smem row stride 80B (32 bf16 + 8 pad) -> conflict-free ldmatrix.
#define ROWB      80
#define TILEB     (128*ROWB)       // 10240
#define OFF_AL    TILEB
#define OFF_BH    (2*TILEB)
#define OFF_BL    (3*TILEB)
#define STG       (4*TILEB)        // 40960 per stage
#define G_SMEM    (2*STG)          // 81920

__device__ __forceinline__ void load_tiles(
        uint32_t sb, int t,
        const __nv_bfloat16* __restrict__ Ah, const __nv_bfloat16* __restrict__ Al,
        const __nv_bfloat16* __restrict__ Bh, const __nv_bfloat16* __restrict__ Bl,
        int m0, int n0, int K, int k0) {
    #pragma unroll
    for (int i = 0; i < 2; ++i) {
        int u = t + i*256;
        int row = u >> 2, ch = u & 3;
        uint32_t soff = (uint32_t)(row*ROWB + ch*16);
        size_t ga = (size_t)(m0 + row) * K + k0 + ch*8;
        size_t gb = (size_t)(n0 + row) * K + k0 + ch*8;
        cpa16(sb + soff,          Ah + ga);
        cpa16(sb + OFF_AL + soff, Al + ga);
        cpa16(sb + OFF_BH + soff, Bh + gb);
        cpa16(sb + OFF_BL + soff, Bl + gb);
    }
}

template<int MODE>
__global__ void __launch_bounds__(256) gemm_tc(
        const __nv_bfloat16* __restrict__ Ah, const __nv_bfloat16* __restrict__ Al,
        const __nv_bfloat16* __restrict__ Bh, const __nv_bfloat16* __restrict__ Bl,
        float* __restrict__ C, __nv_bfloat16* __restrict__ Ch,
        __nv_bfloat16* __restrict__ Cl, int M, int K, int N) {
    extern __shared__ char smem[];
    uint32_t sb = smem_to_u32(smem);
    int t = threadIdx.x, wid = t >> 5, lane = t & 31;
    int m0 = blockIdx.y * 128, n0 = blockIdx.x * 128;
    int wm = (wid & 1) * 64;        // warp m offset in CTA tile
    int wn = (wid >> 1) * 32;       // warp n offset

    float acc[4][4][4];
    #pragma unroll
    for (int i = 0; i < 4; ++i)
        #pragma unroll
        for (int j = 0; j < 4; ++j)
            #pragma unroll
            for (int e = 0; e < 4; ++e) acc[i][j][e] = 0.f;

    const int NC = K >> 5;
    load_tiles(sb, t, Ah, Al, Bh, Bl, m0, n0, K, 0);
    CPA_COMMIT();

    for (int c = 0; c < NC; ++c) {
        if (c + 1 < NC) {
            load_tiles(sb + ((c + 1) & 1) * STG, t, Ah, Al, Bh, Bl,
                       m0, n0, K, (c + 1) * 32);
            CPA_COMMIT();
            CPA_WAIT1();
        } else {
            CPA_WAIT0();
        }
        __syncthreads();
        uint32_t st = sb + (c & 1) * STG;
        #pragma unroll
        for (int ks = 0; ks < 2; ++ks) {
            uint32_t bh[2][4], bl[2][4];
            #pragma unroll
            for (int p = 0; p < 2; ++p) {
                uint32_t nrow = (uint32_t)(wn + p*16 + ((lane >> 4) & 1)*8 + (lane & 7));
                uint32_t boff = nrow*ROWB + ks*32 + ((lane >> 3) & 1)*16;
                ldm4(bh[p], st + OFF_BH + boff);
                ldm4(bl[p], st + OFF_BL + boff);
            }
            #pragma unroll
            for (int i = 0; i < 4; ++i) {
                uint32_t arow = (uint32_t)(wm + i*16 + (lane & 15));
                uint32_t aoff = arow*ROWB + ks*32 + (lane >> 4)*16;
                uint32_t ah[4], al[4];
                ldm4(ah, st + aoff);
                ldm4(al, st + OFF_AL + aoff);
                #pragma unroll
                for (int j = 0; j < 4; ++j) {
                    const uint32_t* bhp = &bh[j >> 1][(j & 1) * 2];
                    const uint32_t* blp = &bl[j >> 1][(j & 1) * 2];
                    mma16816(acc[i][j], ah, bhp);
                    mma16816(acc[i][j], al, bhp);
                    mma16816(acc[i][j], ah, blp);
                }
            }
        }
        __syncthreads();
    }

    // ---- epilogue ----
    int qrow = lane >> 2, qcol = (lane & 3) * 2;
    #pragma unroll
    for (int i = 0; i < 4; ++i) {
        #pragma unroll
        for (int half = 0; half < 2; ++half) {
            int r = m0 + wm + i*16 + qrow + half*8;
            size_t rowoff = (size_t)r * N;
            #pragma unroll
            for (int j = 0; j < 4; ++j) {
                int gc = n0 + wn + j*8 + qcol;
                float v0 = acc[i][j][half*2 + 0];
                float v1 = acc[i][j][half*2 + 1];
                if (MODE == 0) {
                    *reinterpret_cast<float2*>(C + rowoff + gc) = make_float2(v0, v1);
                } else if (MODE == 1) {
                    float2 o = *reinterpret_cast<const float2*>(C + rowoff + gc);
                    *reinterpret_cast<float2*>(C + rowoff + gc) =
                        make_float2(o.x + v0, o.y + v1);
                } else {
                    if (MODE == 2) { v0 = fmaxf(v0, 0.f); v1 = fmaxf(v1, 0.f); }
                    __nv_bfloat16 h0, l0, h1, l1;
                    split_bf(v0, h0, l0); split_bf(v1, h1, l1);
                    *reinterpret_cast<uint32_t*>(Ch + rowoff + gc) = pack2(h0, h1);
                    *reinterpret_cast<uint32_t*>(Cl + rowoff + gc) = pack2(l0, l1);
                }
            }
        }
    }
}

// ===================== top-K (exact, stable) =================================
__global__ void __launch_bounds__(256) topk_kernel(const float* __restrict__ A,
                                                   int* __restrict__ topk) {
    __shared__ float vals[512];
    __shared__ float rv[256];
    __shared__ int   ri[256];
    int r = blockIdx.x, t = threadIdx.x;
    vals[t]       = A[(size_t)r*512 + t];
    vals[t + 256] = A[(size_t)r*512 + t + 256];
    __syncthreads();
    for (int it = 0; it < TOPK; ++it) {
        float bv = vals[t]; int bi = t;
        float v2 = vals[t + 256];
        if (v2 > bv) { bv = v2; bi = t + 256; }
        rv[t] = bv; ri[t] = bi;
        __syncthreads();
        for (int s = 128; s > 0; s >>= 1) {
            if (t < s) {
                float ov = rv[t + s]; int oi = ri[t + s];
                if (ov > rv[t] || (ov == rv[t] && oi < ri[t])) { rv[t] = ov; ri[t] = oi; }
            }
            __syncthreads();
        }
        if (t == 0) { topk[r*TOPK + it] = ri[0]; vals[ri[0]] = -3.402823466e38f; }
        __syncthreads();
    }
}

// ===================== embeddings ============================================
__device__ __forceinline__ float pe_val(int pos, int d) {
    int e = d & ~1;
    float div = __expf(-(float)e * (logf(10000.0f) / (float)DIM));
    float ang = (float)pos * div;
    return (d & 1) ? cosf(ang) : sinf(ang);
}
__global__ void __launch_bounds__(256) embed_src_kernel(
        const float* __restrict__ x_c, const float* __restrict__ Wsrc,
        const int* __restrict__ topk, float* __restrict__ src) {
    __shared__ float xs[SEQ];
    int tok = blockIdx.x, t = threadIdx.x;
    int bn = tok / TOPK, kk = tok % TOPK;
    int b = bn / NN, n = bn % NN;
    int node = topk[n*TOPK + kk];
    if (t < SEQ) xs[t] = x_c[((size_t)b*SEQ + t)*NN + node];
    __syncthreads();
    float acc = 0.f;
    #pragma unroll
    for (int s = 0; s < SEQ; ++s) acc += xs[s] * Wsrc[s*DIM + t];
    src[(size_t)tok*DIM + t] = acc * 16.0f + pe_val(kk, t);
}
__global__ void __launch_bounds__(256) embed_tgt_kernel(
        const float* __restrict__ x_c, const float* __restrict__ Wtgt,
        float* __restrict__ tgt) {
    __shared__ float xs[SEQ];
    int bn = blockIdx.x, t = threadIdx.x;
    int b = bn / NN, n = bn % NN;
    if (t < SEQ) xs[t] = x_c[((size_t)b*SEQ + t)*NN + n];
    __syncthreads();
    float acc = 0.f;
    #pragma unroll
    for (int s = 0; s < SEQ; ++s) acc += xs[s] * Wtgt[s*DIM + t];
    float pe0 = (t & 1) ? 1.0f : 0.0f;
    tgt[(size_t)bn*DIM + t] = acc * 16.0f + pe0;
}

// ===================== layernorm + split =====================================
__global__ void __launch_bounds__(256) ln_split_kernel(
        const float* __restrict__ in,
        __nv_bfloat16* __restrict__ oh, __nv_bfloat16* __restrict__ ol) {
    int wid = threadIdx.x >> 5, lane = threadIdx.x & 31;
    size_t row = (size_t)blockIdx.x * 8 + wid;
    const float* p = in + row*DIM;
    float x[8];
    #pragma unroll
    for (int i = 0; i < 8; ++i) x[i] = p[lane + 32*i];
    float s = 0.f;
    #pragma unroll
    for (int i = 0; i < 8; ++i) s += x[i];
    #pragma unroll
    for (int o = 16; o > 0; o >>= 1) s += __shfl_xor_sync(0xffffffffu, s, o);
    float m = s * (1.0f/DIM);
    float v = 0.f;
    #pragma unroll
    for (int i = 0; i < 8; ++i) { float d = x[i] - m; v += d*d; }
    #pragma unroll
    for (int o = 16; o > 0; o >>= 1) v += __shfl_xor_sync(0xffffffffu, v, o);
    float rs = rsqrtf(v * (1.0f/DIM) + 1e-6f);
    #pragma unroll
    for (int i = 0; i < 8; ++i) {
        float y = (x[i] - m) * rs;
        __nv_bfloat16 h, l; split_bf(y, h, l);
        oh[row*DIM + lane + 32*i] = h;
        ol[row*DIM + lane + 32*i] = l;
    }
}

// ===================== encoder self-attention =================================
__global__ void __launch_bounds__(256) enc_attn_kernel(
        const float* __restrict__ Q, const float* __restrict__ Kv,
        const float* __restrict__ V,
        __nv_bfloat16* __restrict__ Oh, __nv_bfloat16* __restrict__ Ol) {
    __shared__ float qs[TOPK*DIM];
    __shared__ float ks[TOPK*DIM];
    __shared__ float vs[TOPK*DIM];
    int bn = blockIdx.x, t = threadIdx.x;
    size_t base = (size_t)bn * TOPK * DIM;
    for (int i = t; i < TOPK*DIM; i += 256) {
        qs[i] = Q[base + i]; ks[i] = Kv[base + i]; vs[i] = V[base + i];
    }
    __syncthreads();
    const float scale = 0.17677669529663687f;
    float sc[8];
    #pragma unroll
    for (int i = 0; i < 8; ++i) {
        int e = t + i*256;
        int h = e >> 8, qi = (e >> 4) & 15, kj = e & 15;
        const float* qp = &qs[qi*DIM + h*DH];
        const float* kp = &ks[kj*DIM + h*DH];
        float d = 0.f;
        #pragma unroll
        for (int x = 0; x < DH; ++x) d += qp[x]*kp[x];
        sc[i] = d * scale;
    }
    __syncthreads();
    float* S = qs;
    #pragma unroll
    for (int i = 0; i < 8; ++i) S[t + i*256] = sc[i];
    __syncthreads();
    if (t < 128) {
        float* row = &S[t*16];
        float mx = row[0];
        #pragma unroll
        for (int j = 1; j < 16; ++j) mx = fmaxf(mx, row[j]);
        float sum = 0.f;
        #pragma unroll
        for (int j = 0; j < 16; ++j) { float a = expf(row[j]-mx); row[j] = a; sum += a; }
        float inv = 1.0f / sum;
        #pragma unroll
        for (int j = 0; j < 16; ++j) row[j] *= inv;
    }
    __syncthreads();
    for (int i = t; i < TOPK*DIM; i += 256) {
        int qi = i >> 8, c = i & 255, h = c >> 5;
        const float* row = &S[(h*16 + qi)*16];
        float acc = 0.f;
        #pragma unroll
        for (int kj = 0; kj < 16; ++kj) acc += row[kj] * vs[kj*DIM + c];
        __nv_bfloat16 hh, ll; split_bf(acc, hh, ll);
        Oh[base + i] = hh; Ol[base + i] = ll;
    }
}

// ===================== decoder cross-attention ================================
__global__ void __launch_bounds__(256) cross_attn_kernel(
        const float* __restrict__ Q, const float* __restrict__ Kv,
        const float* __restrict__ V,
        __nv_bfloat16* __restrict__ Oh, __nv_bfloat16* __restrict__ Ol) {
    __shared__ float ks[TOPK*DIM];
    __shared__ float vs[TOPK*DIM];
    __shared__ float qv[DIM];
    __shared__ float S[NH*TOPK];
    int bn = blockIdx.x, t = threadIdx.x;
    size_t kb = (size_t)bn * TOPK * DIM;
    qv[t] = Q[(size_t)bn*DIM + t];
    for (int i = t; i < TOPK*DIM; i += 256) { ks[i] = Kv[kb + i]; vs[i] = V[kb + i]; }
    __syncthreads();
    const float scale = 0.17677669529663687f;
    if (t < NH*TOPK) {
        int h = t >> 4, kj = t & 15;
        float d = 0.f;
        #pragma unroll
        for (int x = 0; x < DH; ++x) d += qv[h*DH + x] * ks[kj*DIM + h*DH + x];
        S[t] = d * scale;
    }
    __syncthreads();
    if (t < NH) {
        float* row = &S[t*16];
        float mx = row[0];
        #pragma unroll
        for (int j = 1; j < 16; ++j) mx = fmaxf(mx, row[j]);
        float sum = 0.f;
        #pragma unroll
        for (int j = 0; j < 16; ++j) { float a = expf(row[j]-mx); row[j] = a; sum += a; }
        float inv = 1.0f / sum;
        #pragma unroll
        for (int j = 0; j < 16; ++j) row[j] *= inv;
    }
    __syncthreads();
    {
        int c = t, h = c >> 5;
        float acc = 0.f;
        #pragma unroll
        for (int kj = 0; kj < 16; ++kj) acc += S[h*16 + kj] * vs[kj*DIM + c];
        __nv_bfloat16 hh, ll; split_bf(acc, hh, ll);
        Oh[(size_t)bn*DIM + c] = hh; Ol[(size_t)bn*DIM + c] = ll;
    }
}

// ===================== final LN + generator ==================================
__global__ void __launch_bounds__(256) gen_kernel(
        const float* __restrict__ tgt, const float* __restrict__ Wgen,
        float* __restrict__ out) {
    __shared__ float red[256];
    __shared__ float y[256];
    __shared__ float stat[2];
    int bn = blockIdx.x, t = threadIdx.x;
    float v = tgt[(size_t)bn*DIM + t];
    red[t] = v; __syncthreads();
    for (int s = 128; s > 0; s >>= 1) { if (t < s) red[t] += red[t + s]; __syncthreads(); }
    if (t == 0) stat[0] = red[0] * (1.0f/DIM);
    __syncthreads();
    float d = v - stat[0];
    red[t] = d*d; __syncthreads();
    for (int s = 128; s > 0; s >>= 1) { if (t < s) red[t] += red[t + s]; __syncthreads(); }
    if (t == 0) stat[1] = rsqrtf(red[0] * (1.0f/DIM) + 1e-6f);
    __syncthreads();
    y[t] = d * stat[1];
    __syncthreads();
    if (t < SEQ) {
        float acc = 0.f;
        for (int dd = 0; dd < DIM; ++dd) acc += y[dd] * Wgen[dd*SEQ + t];
        out[(size_t)bn*SEQ + t] = acc;
    }
}

// ===================== host orchestration ====================================
static inline dim3 ggrid(int M, int N) { return dim3(N/128, M/128); }

extern "C" void kernel_launch(void* const* d_in, const int* in_sizes, int n_in,
                              void* d_out, int out_size) {
    (void)in_sizes; (void)n_in; (void)out_size;
    const float* x_c      = (const float*)d_in[0];
    const float* A        = (const float*)d_in[1];
    const float* Wsrc     = (const float*)d_in[2];
    const float* Wtgt     = (const float*)d_in[3];
    const float* enc_attn = (const float*)d_in[4];
    const float* enc_ffn1 = (const float*)d_in[5];
    const float* enc_ffn2 = (const float*)d_in[6];
    const float* dec_self = (const float*)d_in[7];
    const float* dec_cross= (const float*)d_in[8];
    const float* dec_ffn1 = (const float*)d_in[9];
    const float* dec_ffn2 = (const float*)d_in[10];
    const float* Wgen     = (const float*)d_in[11];
    float* out = (float*)d_out;

    float *src,*q,*k,*v,*tgt,*t1; int* topk;
    __nv_bfloat16 *yh,*yl,*memh,*meml,*ffnh,*ffnl,*tyh,*tyl,*t1h,*t1l,*t2h,*t2l,*tfh,*tfl,*wh,*wl;
    cudaGetSymbolAddress((void**)&src,  g_src);
    cudaGetSymbolAddress((void**)&q,    g_q);
    cudaGetSymbolAddress((void**)&k,    g_k);
    cudaGetSymbolAddress((void**)&v,    g_v);
    cudaGetSymbolAddress((void**)&tgt,  g_tgt);
    cudaGetSymbolAddress((void**)&t1,   g_t1);
    cudaGetSymbolAddress((void**)&topk, g_topk);
    cudaGetSymbolAddress((void**)&yh,   g_yh);
    cudaGetSymbolAddress((void**)&yl,   g_yl);
    cudaGetSymbolAddress((void**)&memh, g_memh);
    cudaGetSymbolAddress((void**)&meml, g_meml);
    cudaGetSymbolAddress((void**)&ffnh, g_ffnh);
    cudaGetSymbolAddress((void**)&ffnl, g_ffnl);
    cudaGetSymbolAddress((void**)&tyh,  g_tyh);
    cudaGetSymbolAddress((void**)&tyl,  g_tyl);
    cudaGetSymbolAddress((void**)&t1h,  g_t1h);
    cudaGetSymbolAddress((void**)&t1l,  g_t1l);
    cudaGetSymbolAddress((void**)&t2h,  g_t2h);
    cudaGetSymbolAddress((void**)&t2l,  g_t2l);
    cudaGetSymbolAddress((void**)&tfh,  g_tfh);
    cudaGetSymbolAddress((void**)&tfl,  g_tfl);
    cudaGetSymbolAddress((void**)&wh,   g_wh);
    cudaGetSymbolAddress((void**)&wl,   g_wl);

    cudaFuncSetAttribute(gemm_tc<0>, cudaFuncAttributeMaxDynamicSharedMemorySize, G_SMEM);
    cudaFuncSetAttribute(gemm_tc<1>, cudaFuncAttributeMaxDynamicSharedMemorySize, G_SMEM);
    cudaFuncSetAttribute(gemm_tc<2>, cudaFuncAttributeMaxDynamicSharedMemorySize, G_SMEM);
    cudaFuncSetAttribute(gemm_tc<3>, cudaFuncAttributeMaxDynamicSharedMemorySize, G_SMEM);

    const size_t WSZ = (size_t)DIM*DIM;       // 65536
    const size_t FSZ = (size_t)DIM*DFF;       // 262144

    // ---- weight prep (transpose + bf16 split) ----
    for (int i = 0; i < 8; ++i) {
        wsplit_kernel<<<dim3(DIM/32, DIM/32), 256>>>(enc_attn + i*WSZ,
            wh + W_ENC_ATTN + i*WSZ, wl + W_ENC_ATTN + i*WSZ, DIM, DIM);
        wsplit_kernel<<<dim3(DIM/32, DIM/32), 256>>>(dec_self + i*WSZ,
            wh + W_DEC_SELF + i*WSZ, wl + W_DEC_SELF + i*WSZ, DIM, DIM);
        wsplit_kernel<<<dim3(DIM/32, DIM/32), 256>>>(dec_cross + i*WSZ,
            wh + W_DEC_CROSS + i*WSZ, wl + W_DEC_CROSS + i*WSZ, DIM, DIM);
    }
    for (int l = 0; l < NL; ++l) {
        wsplit_kernel<<<dim3(DFF/32, DIM/32), 256>>>(enc_ffn1 + l*FSZ,
            wh + W_ENC_FFN1 + l*FSZ, wl + W_ENC_FFN1 + l*FSZ, DIM, DFF);
        wsplit_kernel<<<dim3(DIM/32, DFF/32), 256>>>(enc_ffn2 + l*FSZ,
            wh + W_ENC_FFN2 + l*FSZ, wl + W_ENC_FFN2 + l*FSZ, DFF, DIM);
        wsplit_kernel<<<dim3(DFF/32, DIM/32), 256>>>(dec_ffn1 + l*FSZ,
            wh + W_DEC_FFN1 + l*FSZ, wl + W_DEC_FFN1 + l*FSZ, DIM, DFF);
        wsplit_kernel<<<dim3(DIM/32, DFF/32), 256>>>(dec_ffn2 + l*FSZ,
            wh + W_DEC_FFN2 + l*FSZ, wl + W_DEC_FFN2 + l*FSZ, DFF, DIM);
    }

    topk_kernel<<<NN, 256>>>(A, topk);
    embed_src_kernel<<<ME, 256>>>(x_c, Wsrc, topk, src);
    embed_tgt_kernel<<<NB, 256>>>(x_c, Wtgt, tgt);

    // ---- encoder ----
    for (int l = 0; l < NL; ++l) {
        const __nv_bfloat16* Wq_h = wh + W_ENC_ATTN + ((size_t)l*4 + 0)*WSZ;
        const __nv_bfloat16* Wq_l = wl + W_ENC_ATTN + ((size_t)l*4 + 0)*WSZ;
        const __nv_bfloat16* Wk_h = wh + W_ENC_ATTN + ((size_t)l*4 + 1)*WSZ;
        const __nv_bfloat16* Wk_l = wl + W_ENC_ATTN + ((size_t)l*4 + 1)*WSZ;
        const __nv_bfloat16* Wv_h = wh + W_ENC_ATTN + ((size_t)l*4 + 2)*WSZ;
        const __nv_bfloat16* Wv_l = wl + W_ENC_ATTN + ((size_t)l*4 + 2)*WSZ;
        const __nv_bfloat16* Wo_h = wh + W_ENC_ATTN + ((size_t)l*4 + 3)*WSZ;
        const __nv_bfloat16* Wo_l = wl + W_ENC_ATTN + ((size_t)l*4 + 3)*WSZ;

        ln_split_kernel<<<ME/8, 256>>>(src, yh, yl);
        gemm_tc<0><<<ggrid(ME,DIM), 256, G_SMEM>>>(yh, yl, Wq_h, Wq_l, q, nullptr, nullptr, ME, DIM, DIM);
        gemm_tc<0><<<ggrid(ME,DIM), 256, G_SMEM>>>(yh, yl, Wk_h, Wk_l, k, nullptr, nullptr, ME, DIM, DIM);
        gemm_tc<0><<<ggrid(ME,DIM), 256, G_SMEM>>>(yh, yl, Wv_h, Wv_l, v, nullptr, nullptr, ME, DIM, DIM);
        enc_attn_kernel<<<NB, 256>>>(q, k, v, yh, yl);
        gemm_tc<1><<<ggrid(ME,DIM), 256, G_SMEM>>>(yh, yl, Wo_h, Wo_l, src, nullptr, nullptr, ME, DIM, DIM);
        ln_split_kernel<<<ME/8, 256>>>(src, yh, yl);
        gemm_tc<2><<<ggrid(ME,DFF), 256, G_SMEM>>>(yh, yl,
            wh + W_ENC_FFN1 + l*FSZ, wl + W_ENC_FFN1 + l*FSZ,
            nullptr, ffnh, ffnl, ME, DIM, DFF);
        gemm_tc<1><<<ggrid(ME,DIM), 256, G_SMEM>>>(ffnh, ffnl,
            wh + W_ENC_FFN2 + l*FSZ, wl + W_ENC_FFN2 + l*FSZ,
            src, nullptr, nullptr, ME, DFF, DIM);
    }
    ln_split_kernel<<<ME/8, 256>>>(src, memh, meml);

    // ---- decoder ----
    for (int l = 0; l < NL; ++l) {
        // self-attn with seq len 1: softmax == 1 -> o = v
        const __nv_bfloat16* Wsv_h = wh + W_DEC_SELF + ((size_t)l*4 + 2)*WSZ;
        const __nv_bfloat16* Wsv_l = wl + W_DEC_SELF + ((size_t)l*4 + 2)*WSZ;
        const __nv_bfloat16* Wso_h = wh + W_DEC_SELF + ((size_t)l*4 + 3)*WSZ;
        const __nv_bfloat16* Wso_l = wl + W_DEC_SELF + ((size_t)l*4 + 3)*WSZ;
        ln_split_kernel<<<NB/8, 256>>>(tgt, tyh, tyl);
        gemm_tc<3><<<ggrid(NB,DIM), 256, G_SMEM>>>(tyh, tyl, Wsv_h, Wsv_l, nullptr, t1h, t1l, NB, DIM, DIM);
        gemm_tc<1><<<ggrid(NB,DIM), 256, G_SMEM>>>(t1h, t1l, Wso_h, Wso_l, tgt, nullptr, nullptr, NB, DIM, DIM);
        // cross-attn
        const __nv_bfloat16* Wcq_h = wh + W_DEC_CROSS + ((size_t)l*4 + 0)*WSZ;
        const __nv_bfloat16* Wcq_l = wl + W_DEC_CROSS + ((size_t)l*4 + 0)*WSZ;
        const __nv_bfloat16* Wck_h = wh + W_DEC_CROSS + ((size_t)l*4 + 1)*WSZ;
        const __nv_bfloat16* Wck_l = wl + W_DEC_CROSS + ((size_t)l*4 + 1)*WSZ;
        const __nv_bfloat16* Wcv_h = wh + W_DEC_CROSS + ((size_t)l*4 + 2)*WSZ;
        const __nv_bfloat16* Wcv_l = wl + W_DEC_CROSS + ((size_t)l*4 + 2)*WSZ;
        const __nv_bfloat16* Wco_h = wh + W_DEC_CROSS + ((size_t)l*4 + 3)*WSZ;
        const __nv_bfloat16* Wco_l = wl + W_DEC_CROSS + ((size_t)l*4 + 3)*WSZ;
        ln_split_kernel<<<NB/8, 256>>>(tgt, tyh, tyl);
        gemm_tc<0><<<ggrid(NB,DIM), 256, G_SMEM>>>(tyh, tyl, Wcq_h, Wcq_l, t1, nullptr, nullptr, NB, DIM, DIM);
        gemm_tc<0><<<ggrid(ME,DIM), 256, G_SMEM>>>(memh, meml, Wck_h, Wck_l, k, nullptr, nullptr, ME, DIM, DIM);
        gemm_tc<0><<<ggrid(ME,DIM), 256, G_SMEM>>>(memh, meml, Wcv_h, Wcv_l, v, nullptr, nullptr, ME, DIM, DIM);
        cross_attn_kernel<<<NB, 256>>>(t1, k, v, t2h, t2l);
        gemm_tc<1><<<ggrid(NB,DIM), 256, G_SMEM>>>(t2h, t2l, Wco_h, Wco_l, tgt, nullptr, nullptr, NB, DIM, DIM);
        // FFN
        ln_split_kernel<<<NB/8, 256>>>(tgt, tyh, tyl);
        gemm_tc<2><<<ggrid(NB,DFF), 256, G_SMEM>>>(tyh, tyl,
            wh + W_DEC_FFN1 + l*FSZ, wl + W_DEC_FFN1 + l*FSZ,
            nullptr, tfh, tfl, NB, DIM, DFF);
        gemm_tc<1><<<ggrid(NB,DIM), 256, G_SMEM>>>(tfh, tfl,
            wh + W_DEC_FFN2 + l*FSZ, wl + W_DEC_FFN2 + l*FSZ,
            tgt, nullptr, nullptr, NB, DFF, DIM);
    }

    gen_kernel<<<NB, 256>>>(tgt, Wgen, out);
}

// round 8
// speedup vs baseline: 2.5982x; 1.5043x over previous
#include <cuda_runtime.h>
#include <cuda_fp16.h>
#include <cstdint>

// Problem constants
#define BSZ   16
#define SEQ   12
#define NN    512
#define DIM   256
#define NH    8
#define NL    2
#define TOPK  16
#define DFF   1024
#define DH    32
#define NB    (BSZ*NN)        // 8192 sequences
#define ME    (NB*TOPK)       // 131072 encoder tokens

#define WSCALE     256.0f
#define INV_WSCALE 0.00390625f

// ===================== helpers ==============================================
__device__ __forceinline__ uint32_t smem_to_u32(const void* p) {
    uint32_t a;
    asm("{ .reg .u64 t; cvta.to.shared.u64 t, %1; cvt.u32.u64 %0, t; }"
        : "=r"(a) : "l"(p));
    return a;
}
__device__ __forceinline__ void cpa16(uint32_t saddr, const void* g) {
    asm volatile("cp.async.cg.shared.global [%0], [%1], 16;\n" :: "r"(saddr), "l"(g));
}
#define CPA_COMMIT()  asm volatile("cp.async.commit_group;\n" ::: "memory")
#define CPA_WAIT1()   asm volatile("cp.async.wait_group 1;\n" ::: "memory")
#define CPA_WAIT0()   asm volatile("cp.async.wait_group 0;\n" ::: "memory")

__device__ __forceinline__ void ldm4(uint32_t* r, uint32_t a) {
    asm volatile("ldmatrix.sync.aligned.m8n8.x4.shared.b16 {%0,%1,%2,%3}, [%4];"
        : "=r"(r[0]), "=r"(r[1]), "=r"(r[2]), "=r"(r[3]) : "r"(a));
}
__device__ __forceinline__ void mma16816(float* c, const uint32_t* a, const uint32_t* b) {
    asm volatile("mma.sync.aligned.m16n8k16.row.col.f32.f16.f16.f32 "
        "{%0,%1,%2,%3}, {%4,%5,%6,%7}, {%8,%9}, {%0,%1,%2,%3};"
        : "+f"(c[0]), "+f"(c[1]), "+f"(c[2]), "+f"(c[3])
        : "r"(a[0]), "r"(a[1]), "r"(a[2]), "r"(a[3]), "r"(b[0]), "r"(b[1]));
}
__device__ __forceinline__ uint32_t packh2(__half a, __half b) {
    __half2 p = __halves2half2(a, b);
    return *reinterpret_cast<uint32_t*>(&p);
}

// ===================== device scratch ========================================
__device__ float  g_src [ (size_t)ME*DIM ];     // encoder residual (fp32)
__device__ float  g_tgt [ (size_t)NB*DIM ];     // decoder residual (fp32)
__device__ int    g_topk[ NN*TOPK ];
__device__ float  g_wc  [ 2*65536 ];            // dec-self combined weights fp32

__device__ __half g_y   [ (size_t)ME*DIM ];     // LN output (fp16)
__device__ __half g_mem [ (size_t)ME*DIM ];     // encoder memory (fp16)
__device__ __half g_qkv [ (size_t)ME*768 ];     // fused q,k,v
__device__ __half g_att [ (size_t)ME*DIM ];     // attention output
__device__ __half g_ffn [ (size_t)ME*DFF ];     // FFN intermediate
__device__ __half g_kv  [ (size_t)ME*512 ];     // fused cross k,v
__device__ __half g_ty  [ (size_t)NB*DIM ];
__device__ __half g_t1  [ (size_t)NB*DIM ];
__device__ __half g_t2  [ (size_t)NB*DIM ];
__device__ __half g_tf  [ (size_t)NB*DFF ];

// weight arena (transposed [N,K] fp16 hi/lo, scaled by 256)
#define OFF_EQKV  0          // 2 x 768*256
#define OFF_EO    393216     // 2 x 256*256
#define OFF_EF1   524288     // 2 x 1024*256
#define OFF_EF2   1048576    // 2 x 256*1024
#define OFF_DSC   1572864    // 2 x 256*256 (combined self)
#define OFF_DCQ   1703936    // 2 x 256*256
#define OFF_DCKV  1835008    // 2 x 512*256
#define OFF_DCO   2097152    // 2 x 256*256
#define OFF_DF1   2228224    // 2 x 1024*256
#define OFF_DF2   2752512    // 2 x 256*1024
#define W_TOTAL   3276800
__device__ __half g_wbh[ W_TOTAL ];
__device__ __half g_wbl[ W_TOTAL ];

// ===================== weight transpose + split (x256) =======================
// in: W[K,N] fp32 row-major; out: [N,K] fp16 hi/lo, scaled by 256
__global__ void __launch_bounds__(256) wsplit_kernel(
        const float* __restrict__ W, __half* __restrict__ Wh,
        __half* __restrict__ Wl, int K, int N) {
    __shared__ float ts[32][33];
    int k0 = blockIdx.y * 32, n0 = blockIdx.x * 32;
    int tx = threadIdx.x & 31, ty = threadIdx.x >> 5;   // 32x8
    #pragma unroll
    for (int i = 0; i < 32; i += 8)
        ts[ty + i][tx] = W[(size_t)(k0 + ty + i) * N + n0 + tx];
    __syncthreads();
    #pragma unroll
    for (int i = 0; i < 32; i += 8) {
        float x = ts[tx][ty + i] * WSCALE;
        __half h = __float2half_rn(x);
        __half l = __float2half_rn(x - __half2float(h));
        size_t o = (size_t)(n0 + ty + i) * K + k0 + tx;
        Wh[o] = h; Wl[o] = l;
    }
}

// dec-self combined: Wc[k,n] = sum_j Wv[k,j] * Wo[j,n]  (all 256x256 fp32)
__global__ void __launch_bounds__(256) wprod_kernel(
        const float* __restrict__ Wv, const float* __restrict__ Wo,
        float* __restrict__ Wc) {
    __shared__ float row[256];
    int k = blockIdx.x, t = threadIdx.x;
    row[t] = Wv[k*256 + t];
    __syncthreads();
    float acc = 0.f;
    for (int j = 0; j < 256; ++j) acc += row[j] * Wo[j*256 + t];
    Wc[k*256 + t] = acc;
}

// ===================== mma.sync fp16 GEMM (2-term B split) ===================
// C[M,N] (op)= (1/256) * A[M,K] * (Bh + Bl)[K,N]
// A fp16 [M,K]; B = weights [N,K] fp16 hi/lo (pre-scaled x256).
// MODE 0: C=AB (fp32)  1: C+=AB (fp32)  2: Ch=relu(AB) fp16  3: Ch=AB fp16
#define ROWB   80
#define TILEB  (128*ROWB)        // 10240
#define OFF_BH TILEB
#define OFF_BL (2*TILEB)
#define STG    (3*TILEB)         // 30720 per stage
#define G_SMEM (2*STG)           // 61440

__device__ __forceinline__ void load_tiles(
        uint32_t sb, int t,
        const __half* __restrict__ A, const __half* __restrict__ Bh,
        const __half* __restrict__ Bl, int m0, int n0, int K, int k0) {
    #pragma unroll
    for (int i = 0; i < 2; ++i) {
        int u = t + i*256;
        int row = u >> 2, ch = u & 3;
        uint32_t soff = (uint32_t)(row*ROWB + ch*16);
        size_t ga = (size_t)(m0 + row) * K + k0 + ch*8;
        size_t gb = (size_t)(n0 + row) * K + k0 + ch*8;
        cpa16(sb + soff,          A  + ga);
        cpa16(sb + OFF_BH + soff, Bh + gb);
        cpa16(sb + OFF_BL + soff, Bl + gb);
    }
}

template<int MODE>
__global__ void __launch_bounds__(256, 2) gemm_tc(
        const __half* __restrict__ A, const __half* __restrict__ Bh,
        const __half* __restrict__ Bl, float* __restrict__ C,
        __half* __restrict__ Ch, int M, int K, int N) {
    extern __shared__ char smem[];
    uint32_t sb = smem_to_u32(smem);
    int t = threadIdx.x, wid = t >> 5, lane = t & 31;
    int m0 = blockIdx.y * 128, n0 = blockIdx.x * 128;
    int wm = (wid & 1) * 64;
    int wn = (wid >> 1) * 32;

    float acc[4][4][4];
    #pragma unroll
    for (int i = 0; i < 4; ++i)
        #pragma unroll
        for (int j = 0; j < 4; ++j)
            #pragma unroll
            for (int e = 0; e < 4; ++e) acc[i][j][e] = 0.f;

    const int NC = K >> 5;
    load_tiles(sb, t, A, Bh, Bl, m0, n0, K, 0);
    CPA_COMMIT();

    for (int c = 0; c < NC; ++c) {
        if (c + 1 < NC) {
            load_tiles(sb + ((c + 1) & 1) * STG, t, A, Bh, Bl, m0, n0, K, (c + 1) * 32);
            CPA_COMMIT();
            CPA_WAIT1();
        } else {
            CPA_WAIT0();
        }
        __syncthreads();
        uint32_t st = sb + (c & 1) * STG;
        #pragma unroll
        for (int ks = 0; ks < 2; ++ks) {
            uint32_t bh[2][4], bl[2][4];
            #pragma unroll
            for (int p = 0; p < 2; ++p) {
                uint32_t nrow = (uint32_t)(wn + p*16 + ((lane >> 4) & 1)*8 + (lane & 7));
                uint32_t boff = nrow*ROWB + ks*32 + ((lane >> 3) & 1)*16;
                ldm4(bh[p], st + OFF_BH + boff);
                ldm4(bl[p], st + OFF_BL + boff);
            }
            #pragma unroll
            for (int i = 0; i < 4; ++i) {
                uint32_t arow = (uint32_t)(wm + i*16 + (lane & 15));
                uint32_t aoff = arow*ROWB + ks*32 + (lane >> 4)*16;
                uint32_t ah[4];
                ldm4(ah, st + aoff);
                #pragma unroll
                for (int j = 0; j < 4; ++j) {
                    mma16816(acc[i][j], ah, &bh[j >> 1][(j & 1) * 2]);
                    mma16816(acc[i][j], ah, &bl[j >> 1][(j & 1) * 2]);
                }
            }
        }
        __syncthreads();
    }

    // ---- epilogue ----
    int qrow = lane >> 2, qcol = (lane & 3) * 2;
    #pragma unroll
    for (int i = 0; i < 4; ++i) {
        #pragma unroll
        for (int half_ = 0; half_ < 2; ++half_) {
            int r = m0 + wm + i*16 + qrow + half_*8;
            size_t rowoff = (size_t)r * N;
            #pragma unroll
            for (int j = 0; j < 4; ++j) {
                int gc = n0 + wn + j*8 + qcol;
                float v0 = acc[i][j][half_*2 + 0] * INV_WSCALE;
                float v1 = acc[i][j][half_*2 + 1] * INV_WSCALE;
                if (MODE == 0) {
                    *reinterpret_cast<float2*>(C + rowoff + gc) = make_float2(v0, v1);
                } else if (MODE == 1) {
                    float2 o = *reinterpret_cast<const float2*>(C + rowoff + gc);
                    *reinterpret_cast<float2*>(C + rowoff + gc) =
                        make_float2(o.x + v0, o.y + v1);
                } else {
                    if (MODE == 2) { v0 = fmaxf(v0, 0.f); v1 = fmaxf(v1, 0.f); }
                    *reinterpret_cast<uint32_t*>(Ch + rowoff + gc) =
                        packh2(__float2half_rn(v0), __float2half_rn(v1));
                }
            }
        }
    }
}

// ===================== top-K (exact, stable) =================================
__global__ void __launch_bounds__(256) topk_kernel(const float* __restrict__ A,
                                                   int* __restrict__ topk) {
    __shared__ float vals[512];
    __shared__ float rv[256];
    __shared__ int   ri[256];
    int r = blockIdx.x, t = threadIdx.x;
    vals[t]       = A[(size_t)r*512 + t];
    vals[t + 256] = A[(size_t)r*512 + t + 256];
    __syncthreads();
    for (int it = 0; it < TOPK; ++it) {
        float bv = vals[t]; int bi = t;
        float v2 = vals[t + 256];
        if (v2 > bv) { bv = v2; bi = t + 256; }
        rv[t] = bv; ri[t] = bi;
        __syncthreads();
        for (int s = 128; s > 0; s >>= 1) {
            if (t < s) {
                float ov = rv[t + s]; int oi = ri[t + s];
                if (ov > rv[t] || (ov == rv[t] && oi < ri[t])) { rv[t] = ov; ri[t] = oi; }
            }
            __syncthreads();
        }
        if (t == 0) { topk[r*TOPK + it] = ri[0]; vals[ri[0]] = -3.402823466e38f; }
        __syncthreads();
    }
}

// ===================== embeddings ============================================
__device__ __forceinline__ float pe_val(int pos, int d) {
    int e = d & ~1;
    float div = __expf(-(float)e * (logf(10000.0f) / (float)DIM));
    float ang = (float)pos * div;
    return (d & 1) ? cosf(ang) : sinf(ang);
}
__global__ void __launch_bounds__(256) embed_src_kernel(
        const float* __restrict__ x_c, const float* __restrict__ Wsrc,
        const int* __restrict__ topk, float* __restrict__ src) {
    __shared__ float xs[SEQ];
    int tok = blockIdx.x, t = threadIdx.x;
    int bn = tok / TOPK, kk = tok % TOPK;
    int b = bn / NN, n = bn % NN;
    int node = topk[n*TOPK + kk];
    if (t < SEQ) xs[t] = x_c[((size_t)b*SEQ + t)*NN + node];
    __syncthreads();
    float acc = 0.f;
    #pragma unroll
    for (int s = 0; s < SEQ; ++s) acc += xs[s] * Wsrc[s*DIM + t];
    src[(size_t)tok*DIM + t] = acc * 16.0f + pe_val(kk, t);
}
__global__ void __launch_bounds__(256) embed_tgt_kernel(
        const float* __restrict__ x_c, const float* __restrict__ Wtgt,
        float* __restrict__ tgt) {
    __shared__ float xs[SEQ];
    int bn = blockIdx.x, t = threadIdx.x;
    int b = bn / NN, n = bn % NN;
    if (t < SEQ) xs[t] = x_c[((size_t)b*SEQ + t)*NN + n];
    __syncthreads();
    float acc = 0.f;
    #pragma unroll
    for (int s = 0; s < SEQ; ++s) acc += xs[s] * Wtgt[s*DIM + t];
    float pe0 = (t & 1) ? 1.0f : 0.0f;
    tgt[(size_t)bn*DIM + t] = acc * 16.0f + pe0;
}

// ===================== layernorm -> fp16 =====================================
__global__ void __launch_bounds__(256) ln_half_kernel(
        const float* __restrict__ in, __half* __restrict__ oh) {
    int wid = threadIdx.x >> 5, lane = threadIdx.x & 31;
    size_t row = (size_t)blockIdx.x * 8 + wid;
    const float* p = in + row*DIM;
    float x[8];
    #pragma unroll
    for (int i = 0; i < 8; ++i) x[i] = p[lane + 32*i];
    float s = 0.f;
    #pragma unroll
    for (int i = 0; i < 8; ++i) s += x[i];
    #pragma unroll
    for (int o = 16; o > 0; o >>= 1) s += __shfl_xor_sync(0xffffffffu, s, o);
    float m = s * (1.0f/DIM);
    float v = 0.f;
    #pragma unroll
    for (int i = 0; i < 8; ++i) { float d = x[i] - m; v += d*d; }
    #pragma unroll
    for (int o = 16; o > 0; o >>= 1) v += __shfl_xor_sync(0xffffffffu, v, o);
    float rs = rsqrtf(v * (1.0f/DIM) + 1e-6f);
    #pragma unroll
    for (int i = 0; i < 8; ++i)
        oh[row*DIM + lane + 32*i] = __float2half_rn((x[i] - m) * rs);
}

// ===================== encoder self-attention (fp16 qkv fused) ===============
__global__ void __launch_bounds__(256) enc_attn_kernel(
        const __half* __restrict__ QKV, __half* __restrict__ O) {
    __shared__ float qs[TOPK*DIM];
    __shared__ float ks[TOPK*DIM];
    __shared__ float vs[TOPK*DIM];
    int bn = blockIdx.x, t = threadIdx.x;
    size_t base = (size_t)bn * TOPK * 768;
    for (int i = t; i < TOPK*DIM; i += 256) {
        int row = i >> 8, c = i & 255;
        size_t ro = base + (size_t)row * 768;
        qs[i] = __half2float(QKV[ro + c]);
        ks[i] = __half2float(QKV[ro + 256 + c]);
        vs[i] = __half2float(QKV[ro + 512 + c]);
    }
    __syncthreads();
    const float scale = 0.17677669529663687f;
    float sc[8];
    #pragma unroll
    for (int i = 0; i < 8; ++i) {
        int e = t + i*256;
        int h = e >> 8, qi = (e >> 4) & 15, kj = e & 15;
        const float* qp = &qs[qi*DIM + h*DH];
        const float* kp = &ks[kj*DIM + h*DH];
        float d = 0.f;
        #pragma unroll
        for (int x = 0; x < DH; ++x) d += qp[x]*kp[x];
        sc[i] = d * scale;
    }
    __syncthreads();
    float* S = qs;
    #pragma unroll
    for (int i = 0; i < 8; ++i) S[t + i*256] = sc[i];
    __syncthreads();
    if (t < 128) {
        float* row = &S[t*16];
        float mx = row[0];
        #pragma unroll
        for (int j = 1; j < 16; ++j) mx = fmaxf(mx, row[j]);
        float sum = 0.f;
        #pragma unroll
        for (int j = 0; j < 16; ++j) { float a = expf(row[j]-mx); row[j] = a; sum += a; }
        float inv = 1.0f / sum;
        #pragma unroll
        for (int j = 0; j < 16; ++j) row[j] *= inv;
    }
    __syncthreads();
    size_t obase = (size_t)bn * TOPK * DIM;
    for (int i = t; i < TOPK*DIM; i += 256) {
        int qi = i >> 8, c = i & 255, h = c >> 5;
        const float* row = &S[(h*16 + qi)*16];
        float acc = 0.f;
        #pragma unroll
        for (int kj = 0; kj < 16; ++kj) acc += row[kj] * vs[kj*DIM + c];
        O[obase + i] = __float2half_rn(acc);
    }
}

// ===================== decoder cross-attention (fp16) ========================
__global__ void __launch_bounds__(256) cross_attn_kernel(
        const __half* __restrict__ Q, const __half* __restrict__ KV,
        __half* __restrict__ O) {
    __shared__ float ks[TOPK*DIM];
    __shared__ float vs[TOPK*DIM];
    __shared__ float qv[DIM];
    __shared__ float S[NH*TOPK];
    int bn = blockIdx.x, t = threadIdx.x;
    size_t kb = (size_t)bn * TOPK * 512;
    qv[t] = __half2float(Q[(size_t)bn*DIM + t]);
    for (int i = t; i < TOPK*DIM; i += 256) {
        int row = i >> 8, c = i & 255;
        size_t ro = kb + (size_t)row * 512;
        ks[i] = __half2float(KV[ro + c]);
        vs[i] = __half2float(KV[ro + 256 + c]);
    }
    __syncthreads();
    const float scale = 0.17677669529663687f;
    if (t < NH*TOPK) {
        int h = t >> 4, kj = t & 15;
        float d = 0.f;
        #pragma unroll
        for (int x = 0; x < DH; ++x) d += qv[h*DH + x] * ks[kj*DIM + h*DH + x];
        S[t] = d * scale;
    }
    __syncthreads();
    if (t < NH) {
        float* row = &S[t*16];
        float mx = row[0];
        #pragma unroll
        for (int j = 1; j < 16; ++j) mx = fmaxf(mx, row[j]);
        float sum = 0.f;
        #pragma unroll
        for (int j = 0; j < 16; ++j) { float a = expf(row[j]-mx); row[j] = a; sum += a; }
        float inv = 1.0f / sum;
        #pragma unroll
        for (int j = 0; j < 16; ++j) row[j] *= inv;
    }
    __syncthreads();
    {
        int c = t, h = c >> 5;
        float acc = 0.f;
        #pragma unroll
        for (int kj = 0; kj < 16; ++kj) acc += S[h*16 + kj] * vs[kj*DIM + c];
        O[(size_t)bn*DIM + c] = __float2half_rn(acc);
    }
}

// ===================== final LN + generator ==================================
__global__ void __launch_bounds__(256) gen_kernel(
        const float* __restrict__ tgt, const float* __restrict__ Wgen,
        float* __restrict__ out) {
    __shared__ float red[256];
    __shared__ float y[256];
    __shared__ float stat[2];
    int bn = blockIdx.x, t = threadIdx.x;
    float v = tgt[(size_t)bn*DIM + t];
    red[t] = v; __syncthreads();
    for (int s = 128; s > 0; s >>= 1) { if (t < s) red[t] += red[t + s]; __syncthreads(); }
    if (t == 0) stat[0] = red[0] * (1.0f/DIM);
    __syncthreads();
    float d = v - stat[0];
    red[t] = d*d; __syncthreads();
    for (int s = 128; s > 0; s >>= 1) { if (t < s) red[t] += red[t + s]; __syncthreads(); }
    if (t == 0) stat[1] = rsqrtf(red[0] * (1.0f/DIM) + 1e-6f);
    __syncthreads();
    y[t] = d * stat[1];
    __syncthreads();
    if (t < SEQ) {
        float acc = 0.f;
        for (int dd = 0; dd < DIM; ++dd) acc += y[dd] * Wgen[dd*SEQ + t];
        out[(size_t)bn*SEQ + t] = acc;
    }
}

// ===================== host orchestration ====================================
static inline dim3 ggrid(int M, int N) { return dim3(N/128, M/128); }

extern "C" void kernel_launch(void* const* d_in, const int* in_sizes, int n_in,
                              void* d_out, int out_size) {
    (void)in_sizes; (void)n_in; (void)out_size;
    const float* x_c      = (const float*)d_in[0];
    const float* A        = (const float*)d_in[1];
    const float* Wsrc     = (const float*)d_in[2];
    const float* Wtgt     = (const float*)d_in[3];
    const float* enc_attn = (const float*)d_in[4];
    const float* enc_ffn1 = (const float*)d_in[5];
    const float* enc_ffn2 = (const float*)d_in[6];
    const float* dec_self = (const float*)d_in[7];
    const float* dec_cross= (const float*)d_in[8];
    const float* dec_ffn1 = (const float*)d_in[9];
    const float* dec_ffn2 = (const float*)d_in[10];
    const float* Wgen     = (const float*)d_in[11];
    float* out = (float*)d_out;

    float *src, *tgt, *wc; int* topk;
    __half *y, *mem, *qkv, *att, *ffn, *kv, *ty, *t1, *t2, *tf, *wbh, *wbl;
    cudaGetSymbolAddress((void**)&src,  g_src);
    cudaGetSymbolAddress((void**)&tgt,  g_tgt);
    cudaGetSymbolAddress((void**)&wc,   g_wc);
    cudaGetSymbolAddress((void**)&topk, g_topk);
    cudaGetSymbolAddress((void**)&y,    g_y);
    cudaGetSymbolAddress((void**)&mem,  g_mem);
    cudaGetSymbolAddress((void**)&qkv,  g_qkv);
    cudaGetSymbolAddress((void**)&att,  g_att);
    cudaGetSymbolAddress((void**)&ffn,  g_ffn);
    cudaGetSymbolAddress((void**)&kv,   g_kv);
    cudaGetSymbolAddress((void**)&ty,   g_ty);
    cudaGetSymbolAddress((void**)&t1,   g_t1);
    cudaGetSymbolAddress((void**)&t2,   g_t2);
    cudaGetSymbolAddress((void**)&tf,   g_tf);
    cudaGetSymbolAddress((void**)&wbh,  g_wbh);
    cudaGetSymbolAddress((void**)&wbl,  g_wbl);

    cudaFuncSetAttribute(gemm_tc<0>, cudaFuncAttributeMaxDynamicSharedMemorySize, G_SMEM);
    cudaFuncSetAttribute(gemm_tc<1>, cudaFuncAttributeMaxDynamicSharedMemorySize, G_SMEM);
    cudaFuncSetAttribute(gemm_tc<2>, cudaFuncAttributeMaxDynamicSharedMemorySize, G_SMEM);
    cudaFuncSetAttribute(gemm_tc<3>, cudaFuncAttributeMaxDynamicSharedMemorySize, G_SMEM);

    const size_t WSZ = (size_t)DIM*DIM;       // 65536
    const size_t FSZ = (size_t)DIM*DFF;       // 262144
    dim3 wg16(DIM/32, DIM/32);                // [256,256] weight grid

    // ---- weight prep ----
    for (int l = 0; l < NL; ++l) {
        // encoder fused QKV: rows [0..768) of [768,256]
        for (int s = 0; s < 3; ++s)
            wsplit_kernel<<<wg16, 256>>>(enc_attn + ((size_t)l*4 + s)*WSZ,
                wbh + OFF_EQKV + (size_t)l*768*256 + (size_t)s*256*256,
                wbl + OFF_EQKV + (size_t)l*768*256 + (size_t)s*256*256, DIM, DIM);
        wsplit_kernel<<<wg16, 256>>>(enc_attn + ((size_t)l*4 + 3)*WSZ,
            wbh + OFF_EO + l*WSZ, wbl + OFF_EO + l*WSZ, DIM, DIM);
        wsplit_kernel<<<dim3(DFF/32, DIM/32), 256>>>(enc_ffn1 + l*FSZ,
            wbh + OFF_EF1 + l*FSZ, wbl + OFF_EF1 + l*FSZ, DIM, DFF);
        wsplit_kernel<<<dim3(DIM/32, DFF/32), 256>>>(enc_ffn2 + l*FSZ,
            wbh + OFF_EF2 + l*FSZ, wbl + OFF_EF2 + l*FSZ, DFF, DIM);
        // decoder self combined: Wc = Wv @ Wo
        wprod_kernel<<<256, 256>>>(dec_self + ((size_t)l*4 + 2)*WSZ,
                                   dec_self + ((size_t)l*4 + 3)*WSZ, wc + l*WSZ);
        wsplit_kernel<<<wg16, 256>>>(wc + l*WSZ,
            wbh + OFF_DSC + l*WSZ, wbl + OFF_DSC + l*WSZ, DIM, DIM);
        // decoder cross
        wsplit_kernel<<<wg16, 256>>>(dec_cross + ((size_t)l*4 + 0)*WSZ,
            wbh + OFF_DCQ + l*WSZ, wbl + OFF_DCQ + l*WSZ, DIM, DIM);
        for (int s = 0; s < 2; ++s)
            wsplit_kernel<<<wg16, 256>>>(dec_cross + ((size_t)l*4 + 1 + s)*WSZ,
                wbh + OFF_DCKV + (size_t)l*512*256 + (size_t)s*256*256,
                wbl + OFF_DCKV + (size_t)l*512*256 + (size_t)s*256*256, DIM, DIM);
        wsplit_kernel<<<wg16, 256>>>(dec_cross + ((size_t)l*4 + 3)*WSZ,
            wbh + OFF_DCO + l*WSZ, wbl + OFF_DCO + l*WSZ, DIM, DIM);
        wsplit_kernel<<<dim3(DFF/32, DIM/32), 256>>>(dec_ffn1 + l*FSZ,
            wbh + OFF_DF1 + l*FSZ, wbl + OFF_DF1 + l*FSZ, DIM, DFF);
        wsplit_kernel<<<dim3(DIM/32, DFF/32), 256>>>(dec_ffn2 + l*FSZ,
            wbh + OFF_DF2 + l*FSZ, wbl + OFF_DF2 + l*FSZ, DFF, DIM);
    }

    topk_kernel<<<NN, 256>>>(A, topk);
    embed_src_kernel<<<ME, 256>>>(x_c, Wsrc, topk, src);
    embed_tgt_kernel<<<NB, 256>>>(x_c, Wtgt, tgt);

    // ---- encoder ----
    for (int l = 0; l < NL; ++l) {
        ln_half_kernel<<<ME/8, 256>>>(src, y);
        gemm_tc<3><<<ggrid(ME,768), 256, G_SMEM>>>(y,
            wbh + OFF_EQKV + (size_t)l*768*256, wbl + OFF_EQKV + (size_t)l*768*256,
            nullptr, qkv, ME, DIM, 768);
        enc_attn_kernel<<<NB, 256>>>(qkv, att);
        gemm_tc<1><<<ggrid(ME,DIM), 256, G_SMEM>>>(att,
            wbh + OFF_EO + l*WSZ, wbl + OFF_EO + l*WSZ, src, nullptr, ME, DIM, DIM);
        ln_half_kernel<<<ME/8, 256>>>(src, y);
        gemm_tc<2><<<ggrid(ME,DFF), 256, G_SMEM>>>(y,
            wbh + OFF_EF1 + l*FSZ, wbl + OFF_EF1 + l*FSZ, nullptr, ffn, ME, DIM, DFF);
        gemm_tc<1><<<ggrid(ME,DIM), 256, G_SMEM>>>(ffn,
            wbh + OFF_EF2 + l*FSZ, wbl + OFF_EF2 + l*FSZ, src, nullptr, ME, DFF, DIM);
    }
    ln_half_kernel<<<ME/8, 256>>>(src, mem);

    // ---- decoder ----
    for (int l = 0; l < NL; ++l) {
        // self-attn (seq len 1): tgt += ln(tgt) @ (Wv @ Wo)
        ln_half_kernel<<<NB/8, 256>>>(tgt, ty);
        gemm_tc<1><<<ggrid(NB,DIM), 256, G_SMEM>>>(ty,
            wbh + OFF_DSC + l*WSZ, wbl + OFF_DSC + l*WSZ, tgt, nullptr, NB, DIM, DIM);
        // cross-attn
        ln_half_kernel<<<NB/8, 256>>>(tgt, ty);
        gemm_tc<3><<<ggrid(NB,DIM), 256, G_SMEM>>>(ty,
            wbh + OFF_DCQ + l*WSZ, wbl + OFF_DCQ + l*WSZ, nullptr, t1, NB, DIM, DIM);
        gemm_tc<3><<<ggrid(ME,512), 256, G_SMEM>>>(mem,
            wbh + OFF_DCKV + (size_t)l*512*256, wbl + OFF_DCKV + (size_t)l*512*256,
            nullptr, kv, ME, DIM, 512);
        cross_attn_kernel<<<NB, 256>>>(t1, kv, t2);
        gemm_tc<1><<<ggrid(NB,DIM), 256, G_SMEM>>>(t2,
            wbh + OFF_DCO + l*WSZ, wbl + OFF_DCO + l*WSZ, tgt, nullptr, NB, DIM, DIM);
        // FFN
        ln_half_kernel<<<NB/8, 256>>>(tgt, ty);
        gemm_tc<2><<<ggrid(NB,DFF), 256, G_SMEM>>>(ty,
            wbh + OFF_DF1 + l*FSZ, wbl + OFF_DF1 + l*FSZ, nullptr, tf, NB, DIM, DFF);
        gemm_tc<1><<<ggrid(NB,DIM), 256, G_SMEM>>>(tf,
            wbh + OFF_DF2 + l*FSZ, wbl + OFF_DF2 + l*FSZ, tgt, nullptr, NB, DFF, DIM);
    }

    gen_kernel<<<NB, 256>>>(tgt, Wgen, out);
}

// round 9
// speedup vs baseline: 2.9004x; 1.1163x over previous
#include <cuda_runtime.h>
#include <cuda_fp16.h>
#include <cstdint>

// Problem constants
#define BSZ   16
#define SEQ   12
#define NN    512
#define DIM   256
#define NH    8
#define NL    2
#define TOPK  16
#define DFF   1024
#define DH    32
#define NB    (BSZ*NN)        // 8192 sequences
#define ME    (NB*TOPK)       // 131072 encoder tokens

// ===================== helpers ==============================================
__device__ __forceinline__ uint32_t smem_to_u32(const void* p) {
    uint32_t a;
    asm("{ .reg .u64 t; cvta.to.shared.u64 t, %1; cvt.u32.u64 %0, t; }"
        : "=r"(a) : "l"(p));
    return a;
}
__device__ __forceinline__ void cpa16(uint32_t saddr, const void* g) {
    asm volatile("cp.async.cg.shared.global [%0], [%1], 16;\n" :: "r"(saddr), "l"(g));
}
#define CPA_COMMIT()  asm volatile("cp.async.commit_group;\n" ::: "memory")
#define CPA_WAIT1()   asm volatile("cp.async.wait_group 1;\n" ::: "memory")
#define CPA_WAIT0()   asm volatile("cp.async.wait_group 0;\n" ::: "memory")

__device__ __forceinline__ void ldm4(uint32_t* r, uint32_t a) {
    asm volatile("ldmatrix.sync.aligned.m8n8.x4.shared.b16 {%0,%1,%2,%3}, [%4];"
        : "=r"(r[0]), "=r"(r[1]), "=r"(r[2]), "=r"(r[3]) : "r"(a));
}
__device__ __forceinline__ void mma16816(float* c, const uint32_t* a, const uint32_t* b) {
    asm volatile("mma.sync.aligned.m16n8k16.row.col.f32.f16.f16.f32 "
        "{%0,%1,%2,%3}, {%4,%5,%6,%7}, {%8,%9}, {%0,%1,%2,%3};"
        : "+f"(c[0]), "+f"(c[1]), "+f"(c[2]), "+f"(c[3])
        : "r"(a[0]), "r"(a[1]), "r"(a[2]), "r"(a[3]), "r"(b[0]), "r"(b[1]));
}
__device__ __forceinline__ uint32_t packh2(__half a, __half b) {
    __half2 p = __halves2half2(a, b);
    return *reinterpret_cast<uint32_t*>(&p);
}

// ===================== device scratch ========================================
__device__ float  g_src [ (size_t)ME*DIM ];     // encoder residual (fp32)
__device__ float  g_tgt [ (size_t)NB*DIM ];     // decoder residual (fp32)
__device__ int    g_topk[ NN*TOPK ];
__device__ float  g_wc  [ 2*65536 ];            // dec-self combined weights fp32

__device__ __half g_y   [ (size_t)ME*DIM ];     // LN output (fp16)
__device__ __half g_mem [ (size_t)ME*DIM ];     // encoder memory (fp16)
__device__ __half g_qkv [ (size_t)ME*768 ];     // fused q,k,v
__device__ __half g_att [ (size_t)ME*DIM ];     // attention output
__device__ __half g_ffn [ (size_t)ME*DFF ];     // FFN intermediate
__device__ __half g_ty  [ (size_t)NB*DIM ];
__device__ __half g_U   [ (size_t)NB*2048 ];    // per-head folded q
__device__ __half g_WM  [ (size_t)NB*2048 ];    // per-head weighted memory
__device__ __half g_tf  [ (size_t)NB*DFF ];

// weight arena ([N,K] fp16 row-major, single term)
#define OFF_EQKV  0                      // 2 x 768*256
#define OFF_EO    393216                 // 2 x 256*256
#define OFF_EF1   524288                 // 2 x 1024*256
#define OFF_EF2   1048576                // 2 x 256*1024
#define OFF_DSC   1572864                // 2 x 256*256
#define OFF_DM    1703936                // 2 x 2048*256 (cross score fold)
#define OFF_DN    2752512                // 2 x 256*2048 (cross output fold)
#define OFF_DF1   3801088                // 2 x 1024*256
#define OFF_DF2   4325376                // 2 x 256*1024
#define W_TOTAL   4849664
__device__ __half g_wb[ W_TOTAL ];

// ===================== weight transpose -> fp16 ==============================
// in: W[K,N] fp32 row-major; out: [N,K] fp16 row-major
__global__ void __launch_bounds__(256) wconv_kernel(
        const float* __restrict__ W, __half* __restrict__ Wo, int K, int N) {
    __shared__ float ts[32][33];
    int k0 = blockIdx.y * 32, n0 = blockIdx.x * 32;
    int tx = threadIdx.x & 31, ty = threadIdx.x >> 5;   // 32x8
    #pragma unroll
    for (int i = 0; i < 32; i += 8)
        ts[ty + i][tx] = W[(size_t)(k0 + ty + i) * N + n0 + tx];
    __syncthreads();
    #pragma unroll
    for (int i = 0; i < 32; i += 8)
        Wo[(size_t)(n0 + ty + i) * K + k0 + tx] = __float2half_rn(ts[tx][ty + i]);
}

// dec-self combined: Wc[k,n] = sum_j Wv[k,j] * Wo[j,n]  (256x256 fp32)
__global__ void __launch_bounds__(256) wprod_kernel(
        const float* __restrict__ Wv, const float* __restrict__ Wo,
        float* __restrict__ Wc) {
    __shared__ float row[256];
    int k = blockIdx.x, t = threadIdx.x;
    row[t] = Wv[k*256 + t];
    __syncthreads();
    float acc = 0.f;
    for (int j = 0; j < 256; ++j) acc += row[j] * Wo[j*256 + t];
    Wc[k*256 + t] = acc;
}

// cross score fold: out[n=h*256+j][a] = (1/sqrt(32)) * sum_e Wq[a][h*32+e]*Wk[j][h*32+e]
__global__ void __launch_bounds__(256) mfold_kernel(
        const float* __restrict__ Wq, const float* __restrict__ Wk,
        __half* __restrict__ Mout) {
    int n = blockIdx.x;             // 0..2047
    int h = n >> 8, j = n & 255;
    int t = threadIdx.x;            // a
    __shared__ float wk[32];
    if (t < 32) wk[t] = Wk[j*256 + h*32 + t];
    __syncthreads();
    float acc = 0.f;
    #pragma unroll
    for (int e = 0; e < 32; ++e) acc += Wq[t*256 + h*32 + e] * wk[e];
    Mout[(size_t)n*256 + t] = __float2half_rn(acc * 0.17677669529663687f);
}

// cross output fold: out[n][kk=h*256+j] = sum_e Wv[j][h*32+e]*Wo[h*32+e][n]
__global__ void __launch_bounds__(256) nfold_kernel(
        const float* __restrict__ Wv, const float* __restrict__ Wo,
        __half* __restrict__ Nout) {
    int n = blockIdx.x;             // 0..255
    int t = threadIdx.x;
    __shared__ float col[256];
    col[t] = Wo[t*256 + n];
    __syncthreads();
    for (int kk = t; kk < 2048; kk += 256) {
        int h = kk >> 8, j = kk & 255;
        float acc = 0.f;
        #pragma unroll
        for (int e = 0; e < 32; ++e) acc += Wv[j*256 + h*32 + e] * col[h*32 + e];
        Nout[(size_t)n*2048 + kk] = __float2half_rn(acc);
    }
}

// ===================== mma.sync fp16 GEMM (single term) ======================
// C[M,N] (op)= A[M,K] * B[K,N].  A fp16 [M,K]; B = weights [N,K] fp16.
// MODE 0: C=AB (fp32)  1: C+=AB (fp32)  2: Ch=relu(AB) fp16  3: Ch=AB fp16
#define ROWB   80
#define TILEB  (128*ROWB)        // 10240
#define OFF_B  TILEB
#define STG    (2*TILEB)         // 20480 per stage
#define G_SMEM (2*STG)           // 40960

__device__ __forceinline__ void load_tiles(
        uint32_t sb, int t, const __half* __restrict__ A,
        const __half* __restrict__ B, int m0, int n0, int K, int k0) {
    #pragma unroll
    for (int i = 0; i < 2; ++i) {
        int u = t + i*256;
        int row = u >> 2, ch = u & 3;
        uint32_t soff = (uint32_t)(row*ROWB + ch*16);
        cpa16(sb + soff,         A + (size_t)(m0 + row) * K + k0 + ch*8);
        cpa16(sb + OFF_B + soff, B + (size_t)(n0 + row) * K + k0 + ch*8);
    }
}

template<int MODE>
__global__ void __launch_bounds__(256, 2) gemm_tc(
        const __half* __restrict__ A, const __half* __restrict__ B,
        float* __restrict__ C, __half* __restrict__ Ch, int M, int K, int N) {
    extern __shared__ char smem[];
    uint32_t sb = smem_to_u32(smem);
    int t = threadIdx.x, wid = t >> 5, lane = t & 31;
    int m0 = blockIdx.y * 128, n0 = blockIdx.x * 128;
    int wm = (wid & 1) * 64;
    int wn = (wid >> 1) * 32;

    float acc[4][4][4];
    #pragma unroll
    for (int i = 0; i < 4; ++i)
        #pragma unroll
        for (int j = 0; j < 4; ++j)
            #pragma unroll
            for (int e = 0; e < 4; ++e) acc[i][j][e] = 0.f;

    const int NC = K >> 5;
    load_tiles(sb, t, A, B, m0, n0, K, 0);
    CPA_COMMIT();

    for (int c = 0; c < NC; ++c) {
        if (c + 1 < NC) {
            load_tiles(sb + ((c + 1) & 1) * STG, t, A, B, m0, n0, K, (c + 1) * 32);
            CPA_COMMIT();
            CPA_WAIT1();
        } else {
            CPA_WAIT0();
        }
        __syncthreads();
        uint32_t st = sb + (c & 1) * STG;
        #pragma unroll
        for (int ks = 0; ks < 2; ++ks) {
            uint32_t bh[2][4];
            #pragma unroll
            for (int p = 0; p < 2; ++p) {
                uint32_t nrow = (uint32_t)(wn + p*16 + ((lane >> 4) & 1)*8 + (lane & 7));
                uint32_t boff = nrow*ROWB + ks*32 + ((lane >> 3) & 1)*16;
                ldm4(bh[p], st + OFF_B + boff);
            }
            #pragma unroll
            for (int i = 0; i < 4; ++i) {
                uint32_t arow = (uint32_t)(wm + i*16 + (lane & 15));
                uint32_t aoff = arow*ROWB + ks*32 + (lane >> 4)*16;
                uint32_t ah[4];
                ldm4(ah, st + aoff);
                #pragma unroll
                for (int j = 0; j < 4; ++j)
                    mma16816(acc[i][j], ah, &bh[j >> 1][(j & 1) * 2]);
            }
        }
        __syncthreads();
    }

    // ---- epilogue ----
    int qrow = lane >> 2, qcol = (lane & 3) * 2;
    #pragma unroll
    for (int i = 0; i < 4; ++i) {
        #pragma unroll
        for (int half_ = 0; half_ < 2; ++half_) {
            int r = m0 + wm + i*16 + qrow + half_*8;
            size_t rowoff = (size_t)r * N;
            #pragma unroll
            for (int j = 0; j < 4; ++j) {
                int gc = n0 + wn + j*8 + qcol;
                float v0 = acc[i][j][half_*2 + 0];
                float v1 = acc[i][j][half_*2 + 1];
                if (MODE == 0) {
                    *reinterpret_cast<float2*>(C + rowoff + gc) = make_float2(v0, v1);
                } else if (MODE == 1) {
                    float2 o = *reinterpret_cast<const float2*>(C + rowoff + gc);
                    *reinterpret_cast<float2*>(C + rowoff + gc) =
                        make_float2(o.x + v0, o.y + v1);
                } else {
                    if (MODE == 2) { v0 = fmaxf(v0, 0.f); v1 = fmaxf(v1, 0.f); }
                    *reinterpret_cast<uint32_t*>(Ch + rowoff + gc) =
                        packh2(__float2half_rn(v0), __float2half_rn(v1));
                }
            }
        }
    }
}

// ===================== top-K (exact, stable) =================================
__global__ void __launch_bounds__(256) topk_kernel(const float* __restrict__ A,
                                                   int* __restrict__ topk) {
    __shared__ float vals[512];
    __shared__ float rv[256];
    __shared__ int   ri[256];
    int r = blockIdx.x, t = threadIdx.x;
    vals[t]       = A[(size_t)r*512 + t];
    vals[t + 256] = A[(size_t)r*512 + t + 256];
    __syncthreads();
    for (int it = 0; it < TOPK; ++it) {
        float bv = vals[t]; int bi = t;
        float v2 = vals[t + 256];
        if (v2 > bv) { bv = v2; bi = t + 256; }
        rv[t] = bv; ri[t] = bi;
        __syncthreads();
        for (int s = 128; s > 0; s >>= 1) {
            if (t < s) {
                float ov = rv[t + s]; int oi = ri[t + s];
                if (ov > rv[t] || (ov == rv[t] && oi < ri[t])) { rv[t] = ov; ri[t] = oi; }
            }
            __syncthreads();
        }
        if (t == 0) { topk[r*TOPK + it] = ri[0]; vals[ri[0]] = -3.402823466e38f; }
        __syncthreads();
    }
}

// ===================== embeddings ============================================
__device__ __forceinline__ float pe_val(int pos, int d) {
    int e = d & ~1;
    float div = __expf(-(float)e * (logf(10000.0f) / (float)DIM));
    float ang = (float)pos * div;
    return (d & 1) ? cosf(ang) : sinf(ang);
}
__global__ void __launch_bounds__(256) embed_src_kernel(
        const float* __restrict__ x_c, const float* __restrict__ Wsrc,
        const int* __restrict__ topk, float* __restrict__ src) {
    __shared__ float xs[SEQ];
    int tok = blockIdx.x, t = threadIdx.x;
    int bn = tok / TOPK, kk = tok % TOPK;
    int b = bn / NN, n = bn % NN;
    int node = topk[n*TOPK + kk];
    if (t < SEQ) xs[t] = x_c[((size_t)b*SEQ + t)*NN + node];
    __syncthreads();
    float acc = 0.f;
    #pragma unroll
    for (int s = 0; s < SEQ; ++s) acc += xs[s] * Wsrc[s*DIM + t];
    src[(size_t)tok*DIM + t] = acc * 16.0f + pe_val(kk, t);
}
__global__ void __launch_bounds__(256) embed_tgt_kernel(
        const float* __restrict__ x_c, const float* __restrict__ Wtgt,
        float* __restrict__ tgt) {
    __shared__ float xs[SEQ];
    int bn = blockIdx.x, t = threadIdx.x;
    int b = bn / NN, n = bn % NN;
    if (t < SEQ) xs[t] = x_c[((size_t)b*SEQ + t)*NN + n];
    __syncthreads();
    float acc = 0.f;
    #pragma unroll
    for (int s = 0; s < SEQ; ++s) acc += xs[s] * Wtgt[s*DIM + t];
    float pe0 = (t & 1) ? 1.0f : 0.0f;
    tgt[(size_t)bn*DIM + t] = acc * 16.0f + pe0;
}

// ===================== layernorm -> fp16 =====================================
__global__ void __launch_bounds__(256) ln_half_kernel(
        const float* __restrict__ in, __half* __restrict__ oh) {
    int wid = threadIdx.x >> 5, lane = threadIdx.x & 31;
    size_t row = (size_t)blockIdx.x * 8 + wid;
    const float* p = in + row*DIM;
    float x[8];
    #pragma unroll
    for (int i = 0; i < 8; ++i) x[i] = p[lane + 32*i];
    float s = 0.f;
    #pragma unroll
    for (int i = 0; i < 8; ++i) s += x[i];
    #pragma unroll
    for (int o = 16; o > 0; o >>= 1) s += __shfl_xor_sync(0xffffffffu, s, o);
    float m = s * (1.0f/DIM);
    float v = 0.f;
    #pragma unroll
    for (int i = 0; i < 8; ++i) { float d = x[i] - m; v += d*d; }
    #pragma unroll
    for (int o = 16; o > 0; o >>= 1) v += __shfl_xor_sync(0xffffffffu, v, o);
    float rs = rsqrtf(v * (1.0f/DIM) + 1e-6f);
    #pragma unroll
    for (int i = 0; i < 8; ++i)
        oh[row*DIM + lane + 32*i] = __float2half_rn((x[i] - m) * rs);
}

// ===================== encoder self-attention (fp16 qkv fused) ===============
__global__ void __launch_bounds__(256) enc_attn_kernel(
        const __half* __restrict__ QKV, __half* __restrict__ O) {
    __shared__ float qs[TOPK*DIM];
    __shared__ float ks[TOPK*DIM];
    __shared__ float vs[TOPK*DIM];
    int bn = blockIdx.x, t = threadIdx.x;
    size_t base = (size_t)bn * TOPK * 768;
    for (int i = t; i < TOPK*DIM; i += 256) {
        int row = i >> 8, c = i & 255;
        size_t ro = base + (size_t)row * 768;
        qs[i] = __half2float(QKV[ro + c]);
        ks[i] = __half2float(QKV[ro + 256 + c]);
        vs[i] = __half2float(QKV[ro + 512 + c]);
    }
    __syncthreads();
    const float scale = 0.17677669529663687f;
    float sc[8];
    #pragma unroll
    for (int i = 0; i < 8; ++i) {
        int e = t + i*256;
        int h = e >> 8, qi = (e >> 4) & 15, kj = e & 15;
        const float* qp = &qs[qi*DIM + h*DH];
        const float* kp = &ks[kj*DIM + h*DH];
        float d = 0.f;
        #pragma unroll
        for (int x = 0; x < DH; ++x) d += qp[x]*kp[x];
        sc[i] = d * scale;
    }
    __syncthreads();
    float* S = qs;
    #pragma unroll
    for (int i = 0; i < 8; ++i) S[t + i*256] = sc[i];
    __syncthreads();
    if (t < 128) {
        float* row = &S[t*16];
        float mx = row[0];
        #pragma unroll
        for (int j = 1; j < 16; ++j) mx = fmaxf(mx, row[j]);
        float sum = 0.f;
        #pragma unroll
        for (int j = 0; j < 16; ++j) { float a = expf(row[j]-mx); row[j] = a; sum += a; }
        float inv = 1.0f / sum;
        #pragma unroll
        for (int j = 0; j < 16; ++j) row[j] *= inv;
    }
    __syncthreads();
    size_t obase = (size_t)bn * TOPK * DIM;
    for (int i = t; i < TOPK*DIM; i += 256) {
        int qi = i >> 8, c = i & 255, h = c >> 5;
        const float* row = &S[(h*16 + qi)*16];
        float acc = 0.f;
        #pragma unroll
        for (int kj = 0; kj < 16; ++kj) acc += row[kj] * vs[kj*DIM + c];
        O[obase + i] = __float2half_rn(acc);
    }
}

// ===================== decoder cross-attention (folded) ======================
// Per (b,n): scores s_hk = U[bn, h*256:...] . mem_k ; softmax over k;
// WM[bn, h*256+c] = sum_k a_hk * mem_k[c]
__global__ void __launch_bounds__(256) cross2_kernel(
        const __half* __restrict__ U, const __half* __restrict__ Mem,
        __half* __restrict__ WM) {
    __shared__ float ms[TOPK*DIM];     // 16KB
    __shared__ float us[2048];         // 8KB
    __shared__ float S[NH*TOPK];
    int bn = blockIdx.x, t = threadIdx.x;
    size_t mb = (size_t)bn * TOPK * DIM;
    size_t ub = (size_t)bn * 2048;
    for (int i = t; i < TOPK*DIM; i += 256) ms[i] = __half2float(Mem[mb + i]);
    for (int i = t; i < 2048; i += 256)     us[i] = __half2float(U[ub + i]);
    __syncthreads();
    if (t < NH*TOPK) {
        int h = t >> 4, kj = t & 15;
        const float* up = &us[h*256];
        const float* mp = &ms[kj*256];
        float d = 0.f;
        #pragma unroll 8
        for (int c = 0; c < 256; ++c) d += up[c] * mp[c];
        S[t] = d;                      // scale folded into M
    }
    __syncthreads();
    if (t < NH) {
        float* row = &S[t*16];
        float mx = row[0];
        #pragma unroll
        for (int j = 1; j < 16; ++j) mx = fmaxf(mx, row[j]);
        float sum = 0.f;
        #pragma unroll
        for (int j = 0; j < 16; ++j) { float a = expf(row[j]-mx); row[j] = a; sum += a; }
        float inv = 1.0f / sum;
        #pragma unroll
        for (int j = 0; j < 16; ++j) row[j] *= inv;
    }
    __syncthreads();
    for (int i = t; i < 2048; i += 256) {
        int h = i >> 8, c = i & 255;
        const float* a = &S[h*16];
        float acc = 0.f;
        #pragma unroll
        for (int kj = 0; kj < 16; ++kj) acc += a[kj] * ms[kj*256 + c];
        WM[ub + i] = __float2half_rn(acc);
    }
}

// ===================== final LN + generator ==================================
__global__ void __launch_bounds__(256) gen_kernel(
        const float* __restrict__ tgt, const float* __restrict__ Wgen,
        float* __restrict__ out) {
    __shared__ float red[256];
    __shared__ float y[256];
    __shared__ float stat[2];
    int bn = blockIdx.x, t = threadIdx.x;
    float v = tgt[(size_t)bn*DIM + t];
    red[t] = v; __syncthreads();
    for (int s = 128; s > 0; s >>= 1) { if (t < s) red[t] += red[t + s]; __syncthreads(); }
    if (t == 0) stat[0] = red[0] * (1.0f/DIM);
    __syncthreads();
    float d = v - stat[0];
    red[t] = d*d; __syncthreads();
    for (int s = 128; s > 0; s >>= 1) { if (t < s) red[t] += red[t + s]; __syncthreads(); }
    if (t == 0) stat[1] = rsqrtf(red[0] * (1.0f/DIM) + 1e-6f);
    __syncthreads();
    y[t] = d * stat[1];
    __syncthreads();
    if (t < SEQ) {
        float acc = 0.f;
        for (int dd = 0; dd < DIM; ++dd) acc += y[dd] * Wgen[dd*SEQ + t];
        out[(size_t)bn*SEQ + t] = acc;
    }
}

// ===================== host orchestration ====================================
static inline dim3 ggrid(int M, int N) { return dim3(N/128, M/128); }

extern "C" void kernel_launch(void* const* d_in, const int* in_sizes, int n_in,
                              void* d_out, int out_size) {
    (void)in_sizes; (void)n_in; (void)out_size;
    const float* x_c      = (const float*)d_in[0];
    const float* A        = (const float*)d_in[1];
    const float* Wsrc     = (const float*)d_in[2];
    const float* Wtgt     = (const float*)d_in[3];
    const float* enc_attn = (const float*)d_in[4];
    const float* enc_ffn1 = (const float*)d_in[5];
    const float* enc_ffn2 = (const float*)d_in[6];
    const float* dec_self = (const float*)d_in[7];
    const float* dec_cross= (const float*)d_in[8];
    const float* dec_ffn1 = (const float*)d_in[9];
    const float* dec_ffn2 = (const float*)d_in[10];
    const float* Wgen     = (const float*)d_in[11];
    float* out = (float*)d_out;

    float *src, *tgt, *wc; int* topk;
    __half *y, *mem, *qkv, *att, *ffn, *ty, *U, *WM, *tf, *wb;
    cudaGetSymbolAddress((void**)&src,  g_src);
    cudaGetSymbolAddress((void**)&tgt,  g_tgt);
    cudaGetSymbolAddress((void**)&wc,   g_wc);
    cudaGetSymbolAddress((void**)&topk, g_topk);
    cudaGetSymbolAddress((void**)&y,    g_y);
    cudaGetSymbolAddress((void**)&mem,  g_mem);
    cudaGetSymbolAddress((void**)&qkv,  g_qkv);
    cudaGetSymbolAddress((void**)&att,  g_att);
    cudaGetSymbolAddress((void**)&ffn,  g_ffn);
    cudaGetSymbolAddress((void**)&ty,   g_ty);
    cudaGetSymbolAddress((void**)&U,    g_U);
    cudaGetSymbolAddress((void**)&WM,   g_WM);
    cudaGetSymbolAddress((void**)&tf,   g_tf);
    cudaGetSymbolAddress((void**)&wb,   g_wb);

    cudaFuncSetAttribute(gemm_tc<0>, cudaFuncAttributeMaxDynamicSharedMemorySize, G_SMEM);
    cudaFuncSetAttribute(gemm_tc<1>, cudaFuncAttributeMaxDynamicSharedMemorySize, G_SMEM);
    cudaFuncSetAttribute(gemm_tc<2>, cudaFuncAttributeMaxDynamicSharedMemorySize, G_SMEM);
    cudaFuncSetAttribute(gemm_tc<3>, cudaFuncAttributeMaxDynamicSharedMemorySize, G_SMEM);

    const size_t WSZ = (size_t)DIM*DIM;       // 65536
    const size_t FSZ = (size_t)DIM*DFF;       // 262144
    dim3 wg16(DIM/32, DIM/32);

    // ---- weight prep ----
    for (int l = 0; l < NL; ++l) {
        for (int s = 0; s < 3; ++s)
            wconv_kernel<<<wg16, 256>>>(enc_attn + ((size_t)l*4 + s)*WSZ,
                wb + OFF_EQKV + (size_t)l*768*256 + (size_t)s*256*256, DIM, DIM);
        wconv_kernel<<<wg16, 256>>>(enc_attn + ((size_t)l*4 + 3)*WSZ,
            wb + OFF_EO + l*WSZ, DIM, DIM);
        wconv_kernel<<<dim3(DFF/32, DIM/32), 256>>>(enc_ffn1 + l*FSZ,
            wb + OFF_EF1 + l*FSZ, DIM, DFF);
        wconv_kernel<<<dim3(DIM/32, DFF/32), 256>>>(enc_ffn2 + l*FSZ,
            wb + OFF_EF2 + l*FSZ, DFF, DIM);
        // decoder self combined: Wc = Wv @ Wo
        wprod_kernel<<<256, 256>>>(dec_self + ((size_t)l*4 + 2)*WSZ,
                                   dec_self + ((size_t)l*4 + 3)*WSZ, wc + l*WSZ);
        wconv_kernel<<<wg16, 256>>>(wc + l*WSZ, wb + OFF_DSC + l*WSZ, DIM, DIM);
        // decoder cross folds
        mfold_kernel<<<2048, 256>>>(dec_cross + ((size_t)l*4 + 0)*WSZ,
                                    dec_cross + ((size_t)l*4 + 1)*WSZ,
                                    wb + OFF_DM + (size_t)l*2048*256);
        nfold_kernel<<<256, 256>>>(dec_cross + ((size_t)l*4 + 2)*WSZ,
                                   dec_cross + ((size_t)l*4 + 3)*WSZ,
                                   wb + OFF_DN + (size_t)l*256*2048);
        wconv_kernel<<<dim3(DFF/32, DIM/32), 256>>>(dec_ffn1 + l*FSZ,
            wb + OFF_DF1 + l*FSZ, DIM, DFF);
        wconv_kernel<<<dim3(DIM/32, DFF/32), 256>>>(dec_ffn2 + l*FSZ,
            wb + OFF_DF2 + l*FSZ, DFF, DIM);
    }

    topk_kernel<<<NN, 256>>>(A, topk);
    embed_src_kernel<<<ME, 256>>>(x_c, Wsrc, topk, src);
    embed_tgt_kernel<<<NB, 256>>>(x_c, Wtgt, tgt);

    // ---- encoder ----
    for (int l = 0; l < NL; ++l) {
        ln_half_kernel<<<ME/8, 256>>>(src, y);
        gemm_tc<3><<<ggrid(ME,768), 256, G_SMEM>>>(y,
            wb + OFF_EQKV + (size_t)l*768*256, nullptr, qkv, ME, DIM, 768);
        enc_attn_kernel<<<NB, 256>>>(qkv, att);
        gemm_tc<1><<<ggrid(ME,DIM), 256, G_SMEM>>>(att,
            wb + OFF_EO + l*WSZ, src, nullptr, ME, DIM, DIM);
        ln_half_kernel<<<ME/8, 256>>>(src, y);
        gemm_tc<2><<<ggrid(ME,DFF), 256, G_SMEM>>>(y,
            wb + OFF_EF1 + l*FSZ, nullptr, ffn, ME, DIM, DFF);
        gemm_tc<1><<<ggrid(ME,DIM), 256, G_SMEM>>>(ffn,
            wb + OFF_EF2 + l*FSZ, src, nullptr, ME, DFF, DIM);
    }
    ln_half_kernel<<<ME/8, 256>>>(src, mem);

    // ---- decoder ----
    for (int l = 0; l < NL; ++l) {
        // self-attn (seq len 1): tgt += ln(tgt) @ (Wv @ Wo)
        ln_half_kernel<<<NB/8, 256>>>(tgt, ty);
        gemm_tc<1><<<ggrid(NB,DIM), 256, G_SMEM>>>(ty,
            wb + OFF_DSC + l*WSZ, tgt, nullptr, NB, DIM, DIM);
        // cross-attn (folded)
        ln_half_kernel<<<NB/8, 256>>>(tgt, ty);
        gemm_tc<3><<<ggrid(NB,2048), 256, G_SMEM>>>(ty,
            wb + OFF_DM + (size_t)l*2048*256, nullptr, U, NB, DIM, 2048);
        cross2_kernel<<<NB, 256>>>(U, mem, WM);
        gemm_tc<1><<<ggrid(NB,DIM), 256, G_SMEM>>>(WM,
            wb + OFF_DN + (size_t)l*256*2048, tgt, nullptr, NB, 2048, DIM);
        // FFN
        ln_half_kernel<<<NB/8, 256>>>(tgt, ty);
        gemm_tc<2><<<ggrid(NB,DFF), 256, G_SMEM>>>(ty,
            wb + OFF_DF1 + l*FSZ, nullptr, tf, NB, DIM, DFF);
        gemm_tc<1><<<ggrid(NB,DIM), 256, G_SMEM>>>(tf,
            wb + OFF_DF2 + l*FSZ, tgt, nullptr, NB, DFF, DIM);
    }

    gen_kernel<<<NB, 256>>>(tgt, Wgen, out);
}

// round 10
// speedup vs baseline: 3.1076x; 1.0714x over previous
#include <cuda_runtime.h>
#include <cuda_fp16.h>
#include <cstdint>

// Problem constants
#define BSZ   16
#define SEQ   12
#define NN    512
#define DIM   256
#define NH    8
#define NL    2
#define TOPK  16
#define DFF   1024
#define DH    32
#define NB    (BSZ*NN)        // 8192 sequences
#define ME    (NB*TOPK)       // 131072 encoder tokens

// ===================== helpers ==============================================
__device__ __forceinline__ uint32_t smem_to_u32(const void* p) {
    uint32_t a;
    asm("{ .reg .u64 t; cvta.to.shared.u64 t, %1; cvt.u32.u64 %0, t; }"
        : "=r"(a) : "l"(p));
    return a;
}
__device__ __forceinline__ void cpa16(uint32_t saddr, const void* g) {
    asm volatile("cp.async.cg.shared.global [%0], [%1], 16;\n" :: "r"(saddr), "l"(g));
}
#define CPA_COMMIT()  asm volatile("cp.async.commit_group;\n" ::: "memory")
#define CPA_WAIT1()   asm volatile("cp.async.wait_group 1;\n" ::: "memory")
#define CPA_WAIT0()   asm volatile("cp.async.wait_group 0;\n" ::: "memory")

__device__ __forceinline__ void ldm4(uint32_t* r, uint32_t a) {
    asm volatile("ldmatrix.sync.aligned.m8n8.x4.shared.b16 {%0,%1,%2,%3}, [%4];"
        : "=r"(r[0]), "=r"(r[1]), "=r"(r[2]), "=r"(r[3]) : "r"(a));
}
__device__ __forceinline__ void mma16816(float* c, const uint32_t* a, const uint32_t* b) {
    asm volatile("mma.sync.aligned.m16n8k16.row.col.f32.f16.f16.f32 "
        "{%0,%1,%2,%3}, {%4,%5,%6,%7}, {%8,%9}, {%0,%1,%2,%3};"
        : "+f"(c[0]), "+f"(c[1]), "+f"(c[2]), "+f"(c[3])
        : "r"(a[0]), "r"(a[1]), "r"(a[2]), "r"(a[3]), "r"(b[0]), "r"(b[1]));
}
__device__ __forceinline__ uint32_t packh2(__half a, __half b) {
    __half2 p = __halves2half2(a, b);
    return *reinterpret_cast<uint32_t*>(&p);
}

// ===================== device scratch ========================================
__device__ __half g_src [ (size_t)ME*DIM ];     // encoder residual (fp16)
__device__ __half g_tgt [ (size_t)NB*DIM ];     // decoder residual (fp16)
__device__ int    g_topk[ NN*TOPK ];
__device__ float  g_wc  [ 2*65536 ];            // dec-self combined weights fp32

__device__ __half g_y   [ (size_t)ME*DIM ];
__device__ __half g_mem [ (size_t)ME*DIM ];
__device__ __half g_qkv [ (size_t)ME*768 ];
__device__ __half g_att [ (size_t)ME*DIM ];
__device__ __half g_ffn [ (size_t)ME*DFF ];
__device__ __half g_ty  [ (size_t)NB*DIM ];
__device__ __half g_U   [ (size_t)NB*2048 ];
__device__ __half g_WM  [ (size_t)NB*2048 ];
__device__ __half g_tf  [ (size_t)NB*DFF ];

// weight arena ([N,K] fp16 row-major)
#define OFF_EQKV  0
#define OFF_EO    393216
#define OFF_EF1   524288
#define OFF_EF2   1048576
#define OFF_DSC   1572864
#define OFF_DM    1703936
#define OFF_DN    2752512
#define OFF_DF1   3801088
#define OFF_DF2   4325376
#define W_TOTAL   4849664
__device__ __half g_wb[ W_TOTAL ];

// ===================== weight transpose -> fp16 ==============================
__global__ void __launch_bounds__(256) wconv_kernel(
        const float* __restrict__ W, __half* __restrict__ Wo, int K, int N) {
    __shared__ float ts[32][33];
    int k0 = blockIdx.y * 32, n0 = blockIdx.x * 32;
    int tx = threadIdx.x & 31, ty = threadIdx.x >> 5;
    #pragma unroll
    for (int i = 0; i < 32; i += 8)
        ts[ty + i][tx] = W[(size_t)(k0 + ty + i) * N + n0 + tx];
    __syncthreads();
    #pragma unroll
    for (int i = 0; i < 32; i += 8)
        Wo[(size_t)(n0 + ty + i) * K + k0 + tx] = __float2half_rn(ts[tx][ty + i]);
}

// dec-self combined: Wc[k,n] = sum_j Wv[k,j] * Wo[j,n]
__global__ void __launch_bounds__(256) wprod_kernel(
        const float* __restrict__ Wv, const float* __restrict__ Wo,
        float* __restrict__ Wc) {
    __shared__ float row[256];
    int k = blockIdx.x, t = threadIdx.x;
    row[t] = Wv[k*256 + t];
    __syncthreads();
    float acc = 0.f;
    for (int j = 0; j < 256; ++j) acc += row[j] * Wo[j*256 + t];
    Wc[k*256 + t] = acc;
}

// cross score fold
__global__ void __launch_bounds__(256) mfold_kernel(
        const float* __restrict__ Wq, const float* __restrict__ Wk,
        __half* __restrict__ Mout) {
    int n = blockIdx.x;
    int h = n >> 8, j = n & 255;
    int t = threadIdx.x;
    __shared__ float wk[32];
    if (t < 32) wk[t] = Wk[j*256 + h*32 + t];
    __syncthreads();
    float acc = 0.f;
    #pragma unroll
    for (int e = 0; e < 32; ++e) acc += Wq[t*256 + h*32 + e] * wk[e];
    Mout[(size_t)n*256 + t] = __float2half_rn(acc * 0.17677669529663687f);
}

// cross output fold
__global__ void __launch_bounds__(256) nfold_kernel(
        const float* __restrict__ Wv, const float* __restrict__ Wo,
        __half* __restrict__ Nout) {
    int n = blockIdx.x;
    int t = threadIdx.x;
    __shared__ float col[256];
    col[t] = Wo[t*256 + n];
    __syncthreads();
    for (int kk = t; kk < 2048; kk += 256) {
        int h = kk >> 8, j = kk & 255;
        float acc = 0.f;
        #pragma unroll
        for (int e = 0; e < 32; ++e) acc += Wv[j*256 + h*32 + e] * col[h*32 + e];
        Nout[(size_t)n*2048 + kk] = __float2half_rn(acc);
    }
}

// ===================== mma.sync fp16 GEMM ====================================
// MODE 1: Cr += AB (fp16 residual)   2: Ch = relu(AB) fp16   3: Ch = AB fp16
#define ROWB 144

template<int BM>
__device__ __forceinline__ void load_tiles(
        uint32_t sb, int t, const __half* __restrict__ A,
        const __half* __restrict__ B, int m0, int n0, int K, int k0) {
    #pragma unroll
    for (int i = 0; i < BM*8/256; ++i) {
        int u = t + i*256;
        int row = u >> 3, ch = u & 7;
        cpa16(sb + (uint32_t)(row*ROWB + ch*16),
              A + (size_t)(m0 + row) * K + k0 + ch*8);
    }
    #pragma unroll
    for (int i = 0; i < 4; ++i) {
        int u = t + i*256;
        int row = u >> 3, ch = u & 7;
        cpa16(sb + (uint32_t)(BM*ROWB + row*ROWB + ch*16),
              B + (size_t)(n0 + row) * K + k0 + ch*8);
    }
}

template<int MODE, int BM>
__global__ void __launch_bounds__(256, 2) gemm_tc(
        const __half* __restrict__ A, const __half* __restrict__ B,
        __half* __restrict__ Cr, __half* __restrict__ Ch, int M, int K, int N) {
    extern __shared__ char smem[];
    constexpr int I = BM / 32;
    constexpr int STGB = (BM + 128) * ROWB;
    uint32_t sb = smem_to_u32(smem);
    int t = threadIdx.x, wid = t >> 5, lane = t & 31;
    int m0 = blockIdx.y * BM, n0 = blockIdx.x * 128;
    int wm = (wid & 1) * (BM / 2);
    int wn = (wid >> 1) * 32;

    float acc[I][4][4];
    #pragma unroll
    for (int i = 0; i < I; ++i)
        #pragma unroll
        for (int j = 0; j < 4; ++j)
            #pragma unroll
            for (int e = 0; e < 4; ++e) acc[i][j][e] = 0.f;

    const int NC = K >> 6;
    load_tiles<BM>(sb, t, A, B, m0, n0, K, 0);
    CPA_COMMIT();

    for (int c = 0; c < NC; ++c) {
        if (c + 1 < NC) {
            load_tiles<BM>(sb + ((c + 1) & 1) * STGB, t, A, B, m0, n0, K, (c + 1) * 64);
            CPA_COMMIT();
            CPA_WAIT1();
        } else {
            CPA_WAIT0();
        }
        __syncthreads();
        uint32_t st = sb + (c & 1) * STGB;
        #pragma unroll
        for (int ks = 0; ks < 4; ++ks) {
            uint32_t bh[2][4];
            #pragma unroll
            for (int p = 0; p < 2; ++p) {
                uint32_t nrow = (uint32_t)(wn + p*16 + ((lane >> 4) & 1)*8 + (lane & 7));
                uint32_t boff = (uint32_t)(BM*ROWB) + nrow*ROWB + ks*32 + ((lane >> 3) & 1)*16;
                ldm4(bh[p], st + boff);
            }
            #pragma unroll
            for (int i = 0; i < I; ++i) {
                uint32_t arow = (uint32_t)(wm + i*16 + (lane & 15));
                uint32_t aoff = arow*ROWB + ks*32 + (lane >> 4)*16;
                uint32_t ah[4];
                ldm4(ah, st + aoff);
                #pragma unroll
                for (int j = 0; j < 4; ++j)
                    mma16816(acc[i][j], ah, &bh[j >> 1][(j & 1) * 2]);
            }
        }
        __syncthreads();
    }

    int qrow = lane >> 2, qcol = (lane & 3) * 2;
    #pragma unroll
    for (int i = 0; i < I; ++i) {
        #pragma unroll
        for (int half_ = 0; half_ < 2; ++half_) {
            int r = m0 + wm + i*16 + qrow + half_*8;
            size_t rowoff = (size_t)r * N;
            #pragma unroll
            for (int j = 0; j < 4; ++j) {
                int gc = n0 + wn + j*8 + qcol;
                float v0 = acc[i][j][half_*2 + 0];
                float v1 = acc[i][j][half_*2 + 1];
                if (MODE == 1) {
                    __half2 o = *reinterpret_cast<const __half2*>(Cr + rowoff + gc);
                    *reinterpret_cast<uint32_t*>(Cr + rowoff + gc) =
                        packh2(__float2half_rn(__half2float(o.x) + v0),
                               __float2half_rn(__half2float(o.y) + v1));
                } else {
                    if (MODE == 2) { v0 = fmaxf(v0, 0.f); v1 = fmaxf(v1, 0.f); }
                    *reinterpret_cast<uint32_t*>(Ch + rowoff + gc) =
                        packh2(__float2half_rn(v0), __float2half_rn(v1));
                }
            }
        }
    }
}

// ===================== top-K (exact, stable) =================================
__global__ void __launch_bounds__(256) topk_kernel(const float* __restrict__ A,
                                                   int* __restrict__ topk) {
    __shared__ float vals[512];
    __shared__ float rv[256];
    __shared__ int   ri[256];
    int r = blockIdx.x, t = threadIdx.x;
    vals[t]       = A[(size_t)r*512 + t];
    vals[t + 256] = A[(size_t)r*512 + t + 256];
    __syncthreads();
    for (int it = 0; it < TOPK; ++it) {
        float bv = vals[t]; int bi = t;
        float v2 = vals[t + 256];
        if (v2 > bv) { bv = v2; bi = t + 256; }
        rv[t] = bv; ri[t] = bi;
        __syncthreads();
        for (int s = 128; s > 0; s >>= 1) {
            if (t < s) {
                float ov = rv[t + s]; int oi = ri[t + s];
                if (ov > rv[t] || (ov == rv[t] && oi < ri[t])) { rv[t] = ov; ri[t] = oi; }
            }
            __syncthreads();
        }
        if (t == 0) { topk[r*TOPK + it] = ri[0]; vals[ri[0]] = -3.402823466e38f; }
        __syncthreads();
    }
}

// ===================== embeddings ============================================
__device__ __forceinline__ float pe_val(int pos, int d) {
    int e = d & ~1;
    float div = __expf(-(float)e * (logf(10000.0f) / (float)DIM));
    float ang = (float)pos * div;
    return (d & 1) ? cosf(ang) : sinf(ang);
}
__global__ void __launch_bounds__(256) embed_src_kernel(
        const float* __restrict__ x_c, const float* __restrict__ Wsrc,
        const int* __restrict__ topk, __half* __restrict__ src) {
    __shared__ float xs[SEQ];
    int tok = blockIdx.x, t = threadIdx.x;
    int bn = tok / TOPK, kk = tok % TOPK;
    int b = bn / NN, n = bn % NN;
    int node = topk[n*TOPK + kk];
    if (t < SEQ) xs[t] = x_c[((size_t)b*SEQ + t)*NN + node];
    __syncthreads();
    float acc = 0.f;
    #pragma unroll
    for (int s = 0; s < SEQ; ++s) acc += xs[s] * Wsrc[s*DIM + t];
    src[(size_t)tok*DIM + t] = __float2half_rn(acc * 16.0f + pe_val(kk, t));
}
__global__ void __launch_bounds__(256) embed_tgt_kernel(
        const float* __restrict__ x_c, const float* __restrict__ Wtgt,
        __half* __restrict__ tgt) {
    __shared__ float xs[SEQ];
    int bn = blockIdx.x, t = threadIdx.x;
    int b = bn / NN, n = bn % NN;
    if (t < SEQ) xs[t] = x_c[((size_t)b*SEQ + t)*NN + n];
    __syncthreads();
    float acc = 0.f;
    #pragma unroll
    for (int s = 0; s < SEQ; ++s) acc += xs[s] * Wtgt[s*DIM + t];
    float pe0 = (t & 1) ? 1.0f : 0.0f;
    tgt[(size_t)bn*DIM + t] = __float2half_rn(acc * 16.0f + pe0);
}

// ===================== layernorm (fp16 -> fp16) ==============================
__global__ void __launch_bounds__(256) ln_half_kernel(
        const __half* __restrict__ in, __half* __restrict__ oh) {
    int wid = threadIdx.x >> 5, lane = threadIdx.x & 31;
    size_t row = (size_t)blockIdx.x * 8 + wid;
    const __half* p = in + row*DIM;
    float x[8];
    #pragma unroll
    for (int i = 0; i < 8; ++i) x[i] = __half2float(p[lane + 32*i]);
    float s = 0.f;
    #pragma unroll
    for (int i = 0; i < 8; ++i) s += x[i];
    #pragma unroll
    for (int o = 16; o > 0; o >>= 1) s += __shfl_xor_sync(0xffffffffu, s, o);
    float m = s * (1.0f/DIM);
    float v = 0.f;
    #pragma unroll
    for (int i = 0; i < 8; ++i) { float d = x[i] - m; v += d*d; }
    #pragma unroll
    for (int o = 16; o > 0; o >>= 1) v += __shfl_xor_sync(0xffffffffu, v, o);
    float rs = rsqrtf(v * (1.0f/DIM) + 1e-6f);
    #pragma unroll
    for (int i = 0; i < 8; ++i)
        oh[row*DIM + lane + 32*i] = __float2half_rn((x[i] - m) * rs);
}

// ===================== encoder self-attention =================================
__global__ void __launch_bounds__(256) enc_attn_kernel(
        const __half* __restrict__ QKV, __half* __restrict__ O) {
    __shared__ float qs[TOPK*DIM];
    __shared__ float ks[TOPK*DIM];
    __shared__ float vs[TOPK*DIM];
    int bn = blockIdx.x, t = threadIdx.x;
    size_t base = (size_t)bn * TOPK * 768;
    for (int i = t; i < TOPK*DIM; i += 256) {
        int row = i >> 8, c = i & 255;
        size_t ro = base + (size_t)row * 768;
        qs[i] = __half2float(QKV[ro + c]);
        ks[i] = __half2float(QKV[ro + 256 + c]);
        vs[i] = __half2float(QKV[ro + 512 + c]);
    }
    __syncthreads();
    const float scale = 0.17677669529663687f;
    float sc[8];
    #pragma unroll
    for (int i = 0; i < 8; ++i) {
        int e = t + i*256;
        int h = e >> 8, qi = (e >> 4) & 15, kj = e & 15;
        const float* qp = &qs[qi*DIM + h*DH];
        const float* kp = &ks[kj*DIM + h*DH];
        float d = 0.f;
        #pragma unroll
        for (int x = 0; x < DH; ++x) d += qp[x]*kp[x];
        sc[i] = d * scale;
    }
    __syncthreads();
    float* S = qs;
    #pragma unroll
    for (int i = 0; i < 8; ++i) S[t + i*256] = sc[i];
    __syncthreads();
    if (t < 128) {
        float* row = &S[t*16];
        float mx = row[0];
        #pragma unroll
        for (int j = 1; j < 16; ++j) mx = fmaxf(mx, row[j]);
        float sum = 0.f;
        #pragma unroll
        for (int j = 0; j < 16; ++j) { float a = expf(row[j]-mx); row[j] = a; sum += a; }
        float inv = 1.0f / sum;
        #pragma unroll
        for (int j = 0; j < 16; ++j) row[j] *= inv;
    }
    __syncthreads();
    size_t obase = (size_t)bn * TOPK * DIM;
    for (int i = t; i < TOPK*DIM; i += 256) {
        int qi = i >> 8, c = i & 255, h = c >> 5;
        const float* row = &S[(h*16 + qi)*16];
        float acc = 0.f;
        #pragma unroll
        for (int kj = 0; kj < 16; ++kj) acc += row[kj] * vs[kj*DIM + c];
        O[obase + i] = __float2half_rn(acc);
    }
}

// ===================== decoder cross-attention (folded) ======================
__global__ void __launch_bounds__(256) cross2_kernel(
        const __half* __restrict__ U, const __half* __restrict__ Mem,
        __half* __restrict__ WM) {
    __shared__ float ms[TOPK*DIM];
    __shared__ float us[2048];
    __shared__ float S[NH*TOPK];
    int bn = blockIdx.x, t = threadIdx.x;
    size_t mb = (size_t)bn * TOPK * DIM;
    size_t ub = (size_t)bn * 2048;
    for (int i = t; i < TOPK*DIM; i += 256) ms[i] = __half2float(Mem[mb + i]);
    for (int i = t; i < 2048; i += 256)     us[i] = __half2float(U[ub + i]);
    __syncthreads();
    if (t < NH*TOPK) {
        int h = t >> 4, kj = t & 15;
        const float* up = &us[h*256];
        const float* mp = &ms[kj*256];
        float d = 0.f;
        #pragma unroll 8
        for (int c = 0; c < 256; ++c) d += up[c] * mp[c];
        S[t] = d;
    }
    __syncthreads();
    if (t < NH) {
        float* row = &S[t*16];
        float mx = row[0];
        #pragma unroll
        for (int j = 1; j < 16; ++j) mx = fmaxf(mx, row[j]);
        float sum = 0.f;
        #pragma unroll
        for (int j = 0; j < 16; ++j) { float a = expf(row[j]-mx); row[j] = a; sum += a; }
        float inv = 1.0f / sum;
        #pragma unroll
        for (int j = 0; j < 16; ++j) row[j] *= inv;
    }
    __syncthreads();
    for (int i = t; i < 2048; i += 256) {
        int h = i >> 8, c = i & 255;
        const float* a = &S[h*16];
        float acc = 0.f;
        #pragma unroll
        for (int kj = 0; kj < 16; ++kj) acc += a[kj] * ms[kj*256 + c];
        WM[ub + i] = __float2half_rn(acc);
    }
}

// ===================== final LN + generator ==================================
__global__ void __launch_bounds__(256) gen_kernel(
        const __half* __restrict__ tgt, const float* __restrict__ Wgen,
        float* __restrict__ out) {
    __shared__ float red[256];
    __shared__ float y[256];
    __shared__ float stat[2];
    int bn = blockIdx.x, t = threadIdx.x;
    float v = __half2float(tgt[(size_t)bn*DIM + t]);
    red[t] = v; __syncthreads();
    for (int s = 128; s > 0; s >>= 1) { if (t < s) red[t] += red[t + s]; __syncthreads(); }
    if (t == 0) stat[0] = red[0] * (1.0f/DIM);
    __syncthreads();
    float d = v - stat[0];
    red[t] = d*d; __syncthreads();
    for (int s = 128; s > 0; s >>= 1) { if (t < s) red[t] += red[t + s]; __syncthreads(); }
    if (t == 0) stat[1] = rsqrtf(red[0] * (1.0f/DIM) + 1e-6f);
    __syncthreads();
    y[t] = d * stat[1];
    __syncthreads();
    if (t < SEQ) {
        float acc = 0.f;
        for (int dd = 0; dd < DIM; ++dd) acc += y[dd] * Wgen[dd*SEQ + t];
        out[(size_t)bn*SEQ + t] = acc;
    }
}

// ===================== host orchestration ====================================
static inline dim3 gg(int M, int N, int BM) { return dim3(N/128, M/BM); }
static inline int smemb(int BM) { return 2 * (BM + 128) * ROWB; }

extern "C" void kernel_launch(void* const* d_in, const int* in_sizes, int n_in,
                              void* d_out, int out_size) {
    (void)in_sizes; (void)n_in; (void)out_size;
    const float* x_c      = (const float*)d_in[0];
    const float* A        = (const float*)d_in[1];
    const float* Wsrc     = (const float*)d_in[2];
    const float* Wtgt     = (const float*)d_in[3];
    const float* enc_attn = (const float*)d_in[4];
    const float* enc_ffn1 = (const float*)d_in[5];
    const float* enc_ffn2 = (const float*)d_in[6];
    const float* dec_self = (const float*)d_in[7];
    const float* dec_cross= (const float*)d_in[8];
    const float* dec_ffn1 = (const float*)d_in[9];
    const float* dec_ffn2 = (const float*)d_in[10];
    const float* Wgen     = (const float*)d_in[11];
    float* out = (float*)d_out;

    float *wc; int* topk;
    __half *src, *tgt, *y, *mem, *qkv, *att, *ffn, *ty, *U, *WM, *tf, *wb;
    cudaGetSymbolAddress((void**)&src,  g_src);
    cudaGetSymbolAddress((void**)&tgt,  g_tgt);
    cudaGetSymbolAddress((void**)&wc,   g_wc);
    cudaGetSymbolAddress((void**)&topk, g_topk);
    cudaGetSymbolAddress((void**)&y,    g_y);
    cudaGetSymbolAddress((void**)&mem,  g_mem);
    cudaGetSymbolAddress((void**)&qkv,  g_qkv);
    cudaGetSymbolAddress((void**)&att,  g_att);
    cudaGetSymbolAddress((void**)&ffn,  g_ffn);
    cudaGetSymbolAddress((void**)&ty,   g_ty);
    cudaGetSymbolAddress((void**)&U,    g_U);
    cudaGetSymbolAddress((void**)&WM,   g_WM);
    cudaGetSymbolAddress((void**)&tf,   g_tf);
    cudaGetSymbolAddress((void**)&wb,   g_wb);

    cudaFuncSetAttribute(gemm_tc<1,128>, cudaFuncAttributeMaxDynamicSharedMemorySize, smemb(128));
    cudaFuncSetAttribute(gemm_tc<2,128>, cudaFuncAttributeMaxDynamicSharedMemorySize, smemb(128));
    cudaFuncSetAttribute(gemm_tc<3,128>, cudaFuncAttributeMaxDynamicSharedMemorySize, smemb(128));
    cudaFuncSetAttribute(gemm_tc<1,64>,  cudaFuncAttributeMaxDynamicSharedMemorySize, smemb(64));
    cudaFuncSetAttribute(gemm_tc<2,64>,  cudaFuncAttributeMaxDynamicSharedMemorySize, smemb(64));
    cudaFuncSetAttribute(gemm_tc<3,64>,  cudaFuncAttributeMaxDynamicSharedMemorySize, smemb(64));

    const size_t WSZ = (size_t)DIM*DIM;
    const size_t FSZ = (size_t)DIM*DFF;
    dim3 wg16(DIM/32, DIM/32);

    // ---- weight prep ----
    for (int l = 0; l < NL; ++l) {
        for (int s = 0; s < 3; ++s)
            wconv_kernel<<<wg16, 256>>>(enc_attn + ((size_t)l*4 + s)*WSZ,
                wb + OFF_EQKV + (size_t)l*768*256 + (size_t)s*256*256, DIM, DIM);
        wconv_kernel<<<wg16, 256>>>(enc_attn + ((size_t)l*4 + 3)*WSZ,
            wb + OFF_EO + l*WSZ, DIM, DIM);
        wconv_kernel<<<dim3(DFF/32, DIM/32), 256>>>(enc_ffn1 + l*FSZ,
            wb + OFF_EF1 + l*FSZ, DIM, DFF);
        wconv_kernel<<<dim3(DIM/32, DFF/32), 256>>>(enc_ffn2 + l*FSZ,
            wb + OFF_EF2 + l*FSZ, DFF, DIM);
        wprod_kernel<<<256, 256>>>(dec_self + ((size_t)l*4 + 2)*WSZ,
                                   dec_self + ((size_t)l*4 + 3)*WSZ, wc + l*WSZ);
        wconv_kernel<<<wg16, 256>>>(wc + l*WSZ, wb + OFF_DSC + l*WSZ, DIM, DIM);
        mfold_kernel<<<2048, 256>>>(dec_cross + ((size_t)l*4 + 0)*WSZ,
                                    dec_cross + ((size_t)l*4 + 1)*WSZ,
                                    wb + OFF_DM + (size_t)l*2048*256);
        nfold_kernel<<<256, 256>>>(dec_cross + ((size_t)l*4 + 2)*WSZ,
                                   dec_cross + ((size_t)l*4 + 3)*WSZ,
                                   wb + OFF_DN + (size_t)l*256*2048);
        wconv_kernel<<<dim3(DFF/32, DIM/32), 256>>>(dec_ffn1 + l*FSZ,
            wb + OFF_DF1 + l*FSZ, DIM, DFF);
        wconv_kernel<<<dim3(DIM/32, DFF/32), 256>>>(dec_ffn2 + l*FSZ,
            wb + OFF_DF2 + l*FSZ, DFF, DIM);
    }

    topk_kernel<<<NN, 256>>>(A, topk);
    embed_src_kernel<<<ME, 256>>>(x_c, Wsrc, topk, src);
    embed_tgt_kernel<<<NB, 256>>>(x_c, Wtgt, tgt);

    // ---- encoder (BM=128) ----
    for (int l = 0; l < NL; ++l) {
        ln_half_kernel<<<ME/8, 256>>>(src, y);
        gemm_tc<3,128><<<gg(ME,768,128), 256, smemb(128)>>>(y,
            wb + OFF_EQKV + (size_t)l*768*256, nullptr, qkv, ME, DIM, 768);
        enc_attn_kernel<<<NB, 256>>>(qkv, att);
        gemm_tc<1,128><<<gg(ME,DIM,128), 256, smemb(128)>>>(att,
            wb + OFF_EO + l*WSZ, src, nullptr, ME, DIM, DIM);
        ln_half_kernel<<<ME/8, 256>>>(src, y);
        gemm_tc<2,128><<<gg(ME,DFF,128), 256, smemb(128)>>>(y,
            wb + OFF_EF1 + l*FSZ, nullptr, ffn, ME, DIM, DFF);
        gemm_tc<1,128><<<gg(ME,DIM,128), 256, smemb(128)>>>(ffn,
            wb + OFF_EF2 + l*FSZ, src, nullptr, ME, DFF, DIM);
    }
    ln_half_kernel<<<ME/8, 256>>>(src, mem);

    // ---- decoder (BM=64) ----
    for (int l = 0; l < NL; ++l) {
        ln_half_kernel<<<NB/8, 256>>>(tgt, ty);
        gemm_tc<1,64><<<gg(NB,DIM,64), 256, smemb(64)>>>(ty,
            wb + OFF_DSC + l*WSZ, tgt, nullptr, NB, DIM, DIM);
        ln_half_kernel<<<NB/8, 256>>>(tgt, ty);
        gemm_tc<3,64><<<gg(NB,2048,64), 256, smemb(64)>>>(ty,
            wb + OFF_DM + (size_t)l*2048*256, nullptr, U, NB, DIM, 2048);
        cross2_kernel<<<NB, 256>>>(U, mem, WM);
        gemm_tc<1,64><<<gg(NB,DIM,64), 256, smemb(64)>>>(WM,
            wb + OFF_DN + (size_t)l*256*2048, tgt, nullptr, NB, 2048, DIM);
        ln_half_kernel<<<NB/8, 256>>>(tgt, ty);
        gemm_tc<2,64><<<gg(NB,DFF,64), 256, smemb(64)>>>(ty,
            wb + OFF_DF1 + l*FSZ, nullptr, tf, NB, DIM, DFF);
        gemm_tc<1,64><<<gg(NB,DIM,64), 256, smemb(64)>>>(tf,
            wb + OFF_DF2 + l*FSZ, tgt, nullptr, NB, DFF, DIM);
    }

    gen_kernel<<<NB, 256>>>(tgt, Wgen, out);
}